// round 7
// baseline (speedup 1.0000x reference)
#include <cuda_runtime.h>
#include <cuda_bf16.h>
#include <math.h>
#include <stdint.h>

#define BB  8
#define DIM 128
#define CL  32
#define HH  256
#define WW  256

#define APITCH 136            // bf16 elems per A row (K padded)
#define APB    (APITCH*2)     // 272 B rows: 17*16 -> ldmatrix-aligned, conflict-free

// ---------------- device scratch ----------------
__device__ float g_S0[BB*CL*HH*WW];
__device__ float g_P1[BB*CL*128*128];
__device__ float g_D1[BB*CL*128*128];
__device__ float g_P2[BB*CL*64*64];
__device__ float g_D2[BB*CL*64*64];
__device__ float g_P3[BB*CL*32*32];
__device__ float g_D3[BB*CL*32*32];

// weight fragments in MMA B-register order: [kt][ntg][lane] -> uint2 {b0,b1}
// sizes: s1 4*8*32, s2 6*12*32, s3 8*16*32
__device__ __align__(16) uint2 g_F1h[4*8*32];
__device__ __align__(16) uint2 g_F1l[4*8*32];
__device__ __align__(16) uint2 g_F2h[6*12*32];
__device__ __align__(16) uint2 g_F2l[6*12*32];
__device__ __align__(16) uint2 g_F3h[8*16*32];
__device__ __align__(16) uint2 g_F3l[8*16*32];

// ---------------- smem layout (fused kernel): 68 KB ----------------
#define OFF_AHI 0
#define OFF_ALO 34816
#define SMEM_REQ 69632

// ---------------- asm helpers ----------------
__device__ __forceinline__ uint32_t smem_u32(const void* p) {
    uint32_t a;
    asm("{ .reg .u64 t; cvta.to.shared.u64 t, %1; cvt.u32.u64 %0, t; }" : "=r"(a) : "l"(p));
    return a;
}
__device__ __forceinline__ void ldsm_x4(uint32_t r[4], uint32_t addr) {
    asm volatile("ldmatrix.sync.aligned.m8n8.x4.shared.b16 {%0,%1,%2,%3}, [%4];"
        : "=r"(r[0]), "=r"(r[1]), "=r"(r[2]), "=r"(r[3]) : "r"(addr));
}
__device__ __forceinline__ void mma16816(float d[4], const uint32_t a[4], uint32_t b0, uint32_t b1) {
    asm volatile("mma.sync.aligned.m16n8k16.row.col.f32.bf16.bf16.f32 "
        "{%0,%1,%2,%3}, {%4,%5,%6,%7}, {%8,%9}, {%0,%1,%2,%3};"
        : "+f"(d[0]), "+f"(d[1]), "+f"(d[2]), "+f"(d[3])
        : "r"(a[0]), "r"(a[1]), "r"(a[2]), "r"(a[3]), "r"(b0), "r"(b1));
}
__device__ __forceinline__ void sts16(uint32_t addr, uint16_t v) {
    asm volatile("st.shared.b16 [%0], %1;" :: "r"(addr), "h"(v) : "memory");
}
__device__ __forceinline__ void sts32(uint32_t addr, uint32_t v) {
    asm volatile("st.shared.b32 [%0], %1;" :: "r"(addr), "r"(v) : "memory");
}
__device__ __forceinline__ void lds128(float& a, float& b, float& c, float& d, uint32_t addr) {
    asm volatile("ld.shared.v4.f32 {%0,%1,%2,%3}, [%4];"
        : "=f"(a), "=f"(b), "=f"(c), "=f"(d) : "r"(addr));
}
__device__ __forceinline__ void splitf(float v, uint16_t& h, uint16_t& l) {
    __nv_bfloat16 hb = __float2bfloat16(v);
    __nv_bfloat16 lb = __float2bfloat16(v - __bfloat162float(hb));
    h = __bfloat16_as_ushort(hb);
    l = __bfloat16_as_ushort(lb);
}

// ---------------- weight prep: shuffle-fold + split + fragment order ----------------
// stage s: shuffled index c -> original col. s1: (c&7)*8 + c/8 ; s2: (c%12)*8 + c/12 ; s3: (c&15)*8 + c/16
__device__ __forceinline__ float wfetch(int s, const float* w1, const float* w2, const float* w3,
                                        int n, int c)
{
    if (s == 0) return w1[(n << 6) + ((c & 7) << 3) + (c >> 3)];
    if (s == 1) return w2[n*96 + (c % 12)*8 + c/12];
    return w3[(n << 7) + ((c & 15) << 3) + (c >> 4)];
}

#define ENT1 (4*8*32)
#define ENT2 (6*12*32)
#define ENT3 (8*16*32)
__global__ void k_prep(const float* __restrict__ w1, const float* __restrict__ w2,
                       const float* __restrict__ w3)
{
    int t = blockIdx.x * blockDim.x + threadIdx.x;
    int s, i; uint2 *fh, *fl; int NTG;
    if (t < ENT1)                  { s = 0; i = t;               fh = g_F1h; fl = g_F1l; NTG = 8;  }
    else if (t < ENT1+ENT2)        { s = 1; i = t - ENT1;        fh = g_F2h; fl = g_F2l; NTG = 12; }
    else if (t < ENT1+ENT2+ENT3)   { s = 2; i = t - ENT1 - ENT2; fh = g_F3h; fl = g_F3l; NTG = 16; }
    else return;

    int lane = i & 31;
    int blk  = i >> 5;            // kt*NTG + ntg
    int kt   = blk / NTG;
    int ntg  = blk - kt*NTG;
    int n    = ntg*8 + (lane >> 2);
    int k0   = kt*16 + 2*(lane & 3);

    uint16_t h[4], l[4];
    #pragma unroll
    for (int j = 0; j < 4; j++) {
        int k = k0 + (j >> 1)*8 + (j & 1);     // k0, k0+1, k0+8, k0+9
        float w = wfetch(s, w1, w2, w3, n, k);
        splitf(w, h[j], l[j]);
    }
    fh[i] = make_uint2((uint32_t)h[0] | ((uint32_t)h[1] << 16),
                       (uint32_t)h[2] | ((uint32_t)h[3] << 16));
    fl[i] = make_uint2((uint32_t)l[0] | ((uint32_t)l[1] << 16),
                       (uint32_t)l[2] | ((uint32_t)l[3] << 16));
}

// ---------------- pools ----------------
template<int KK>
__device__ __forceinline__ void pool_impl(const float* __restrict__ x, int lvl,
                                          float* __restrict__ out)
{
    const int HO = HH / KK;
    int idx = blockIdx.x * blockDim.x + threadIdx.x;
    if (idx >= BB*CL*HO*HO) return;
    int xo = idx % HO;
    int yo = (idx / HO) % HO;
    int c  = (idx / (HO*HO)) % CL;
    int b  = idx / (HO*HO*CL);
    const float* p = x + (((size_t)b*DIM + lvl*CL + c)*HH + (size_t)yo*KK)*WW + (size_t)xo*KK;
    float m = -3.402823466e38f;
    #pragma unroll
    for (int dy = 0; dy < KK; dy++)
        #pragma unroll
        for (int dx = 0; dx < KK; dx++)
            m = fmaxf(m, p[dy*WW + dx]);
    out[idx] = m;
}
__global__ void k_pool2(const float* __restrict__ x){ pool_impl<2>(x, 1, g_P1); }
__global__ void k_pool4(const float* __restrict__ x){ pool_impl<4>(x, 2, g_P2); }
__global__ void k_pool8(const float* __restrict__ x){ pool_impl<8>(x, 3, g_P3); }

// ---------------- depthwise 3x3 (all levels, one kernel) ----------------
__device__ __forceinline__ void dw_one(const float* __restrict__ in, float* __restrict__ out,
                                       const float* __restrict__ w_dw, const float* __restrict__ b_dw,
                                       int lvl, int S, bool from_x, int idx)
{
    int xx = idx % S;
    int yy = (idx / S) % S;
    int c  = (idx / (S*S)) % CL;
    int b  = idx / (S*S*CL);
    const float* ip = from_x ? in + ((size_t)b*DIM + lvl*CL + c) * (size_t)(S*S)
                             : in + ((size_t)b*CL + c) * (size_t)(S*S);
    const float* wp = w_dw + (lvl*CL + c) * 9;
    float acc = b_dw[lvl*CL + c];
    #pragma unroll
    for (int ky = 0; ky < 3; ky++) {
        int iy = yy + ky - 1;
        if ((unsigned)iy >= (unsigned)S) continue;
        #pragma unroll
        for (int kx = 0; kx < 3; kx++) {
            int ix = xx + kx - 1;
            if ((unsigned)ix >= (unsigned)S) continue;
            acc = fmaf(wp[ky*3 + kx], ip[iy*S + ix], acc);
        }
    }
    out[idx] = acc;
}

#define N_DW0 (BB*CL*256*256)
#define N_DW1 (BB*CL*128*128)
#define N_DW2 (BB*CL*64*64)
#define N_DW3 (BB*CL*32*32)
__global__ void k_dwall(const float* __restrict__ x, const float* __restrict__ w,
                        const float* __restrict__ b)
{
    int idx = blockIdx.x * blockDim.x + threadIdx.x;
    if (idx < N_DW0) { dw_one(x, g_S0, w, b, 0, 256, true, idx); return; }
    idx -= N_DW0;
    if (idx < N_DW1) { dw_one(g_P1, g_D1, w, b, 1, 128, false, idx); return; }
    idx -= N_DW1;
    if (idx < N_DW2) { dw_one(g_P2, g_D2, w, b, 2, 64, false, idx); return; }
    idx -= N_DW2;
    if (idx < N_DW3) { dw_one(g_P3, g_D3, w, b, 3, 32, false, idx); return; }
}

// ---------------- GEMM stage: A from smem (ldmatrix), B frags via __ldg (L1-hot) ----------------
// 16 warps: grid 4(M) x 4(N). Warp tile: 32 px x NT*8 out ch. KT k-steps of 16.
template<int NT, int KT, int NTG>
__device__ __forceinline__ void run_stage(uint32_t base,
                                          const uint2* __restrict__ Fh,
                                          const uint2* __restrict__ Fl,
                                          int wm, int wn, int lane, float acc[2][4][4])
{
    #pragma unroll
    for (int mt = 0; mt < 2; mt++)
        #pragma unroll
        for (int nt = 0; nt < NT; nt++)
            #pragma unroll
            for (int i = 0; i < 4; i++) acc[mt][nt][i] = 0.0f;

    const int mbase = wm * 32;
    const uint32_t a_off = (uint32_t)(mbase + (lane & 15)) * APB + ((lane >> 4) << 4);
    const uint32_t AHI = base + OFF_AHI + a_off;
    const uint32_t ALO = base + OFF_ALO + a_off;
    const uint2* FhW = Fh + ((size_t)wn*NT)*32 + lane;
    const uint2* FlW = Fl + ((size_t)wn*NT)*32 + lane;

    #pragma unroll
    for (int kt = 0; kt < KT; kt++) {
        uint32_t ah[2][4], al[2][4];
        #pragma unroll
        for (int mt = 0; mt < 2; mt++) {
            ldsm_x4(ah[mt], AHI + mt*16*APB + kt*32);
            ldsm_x4(al[mt], ALO + mt*16*APB + kt*32);
        }
        #pragma unroll
        for (int nt = 0; nt < NT; nt++) {
            uint2 fh = __ldg(FhW + ((size_t)kt*NTG + nt)*32);
            uint2 fl = __ldg(FlW + ((size_t)kt*NTG + nt)*32);
            #pragma unroll
            for (int mt = 0; mt < 2; mt++) {
                mma16816(acc[mt][nt], ah[mt], fh.x, fh.y);
                mma16816(acc[mt][nt], al[mt], fh.x, fh.y);
                mma16816(acc[mt][nt], ah[mt], fl.x, fl.y);
            }
        }
    }
}

template<int NT>
__device__ __forceinline__ void writeback(uint32_t base, const float* __restrict__ bias,
                                          int wm, int wn, int lane, float acc[2][4][4])
{
    const int mbase = wm * 32;
    const int nbase = wn * NT * 8;
    #pragma unroll
    for (int mt = 0; mt < 2; mt++) {
        int p0 = mbase + mt*16 + (lane >> 2);
        #pragma unroll
        for (int nt = 0; nt < NT; nt++) {
            int o = nbase + nt*8 + (lane & 3)*2;
            float b0 = __ldg(&bias[o]), b1 = __ldg(&bias[o+1]);
            uint16_t h0, l0, h1, l1;
            splitf(acc[mt][nt][0] + b0, h0, l0);
            splitf(acc[mt][nt][1] + b1, h1, l1);
            uint32_t addr = base + (uint32_t)p0*APB + o*2;
            sts32(addr + OFF_AHI, (uint32_t)h0 | ((uint32_t)h1 << 16));
            sts32(addr + OFF_ALO, (uint32_t)l0 | ((uint32_t)l1 << 16));
            splitf(acc[mt][nt][2] + b0, h0, l0);
            splitf(acc[mt][nt][3] + b1, h1, l1);
            addr += 8*APB;
            sts32(addr + OFF_AHI, (uint32_t)h0 | ((uint32_t)h1 << 16));
            sts32(addr + OFF_ALO, (uint32_t)l0 | ((uint32_t)l1 << 16));
        }
    }
}

// ---------------- fused kernel: 512 threads, 16 warps, 2 CTAs/SM ----------------
#define TPC 4
#define NTHR 512
__global__ __launch_bounds__(NTHR, 2)
void fused_mma(const float* __restrict__ x,
               const float* __restrict__ bf1, const float* __restrict__ bf2,
               const float* __restrict__ bf3, float* __restrict__ out)
{
    extern __shared__ __align__(16) unsigned char sm[];
    const uint32_t base = smem_u32(sm);
    const int tid = threadIdx.x;
    const int lane = tid & 31, wid = tid >> 5;
    const int wm = wid >> 2, wn = wid & 3;

    float acc[2][4][4];

    for (int t = 0; t < TPC; t++) {
        int tile = blockIdx.x * TPC + t;
        int b = tile >> 9;
        int rem = (tile & 511) * 128;

        __syncthreads();   // A region free (prev tile epilogue done)

        // ---- build A (128 px x 128 ch, bf16 split) ----
        for (int i = tid; i < 128*128; i += NTHR) {
            int ch = i >> 7, p = i & 127;
            int r = rem + p;
            int y = r >> 8, xx = r & 255;
            float v;
            if (ch < 32)      v = g_S0[((b*32 + ch) << 16) + r];
            else if (ch < 64) v = g_D1[(b*32 + ch-32)*16384 + (y>>1)*128 + (xx>>1)];
            else if (ch < 96) v = g_D2[(b*32 + ch-64)*4096  + (y>>2)*64  + (xx>>2)];
            else              v = g_D3[(b*32 + ch-96)*1024  + (y>>3)*32  + (xx>>3)];
            uint16_t h, l;
            splitf(v, h, l);
            uint32_t addr = base + (uint32_t)p*APB + ch*2;
            sts16(addr + OFF_AHI, h);
            sts16(addr + OFF_ALO, l);
        }
        __syncthreads();

        // ---- stage 1: res1(64) ----
        run_stage<2, 4, 8>(base, g_F1h, g_F1l, wm, wn, lane, acc);
        __syncthreads();
        writeback<2>(base, bf1, wm, wn, lane, acc);
        __syncthreads();

        // ---- stage 2: res2(96) ----
        run_stage<3, 6, 12>(base, g_F2h, g_F2l, wm, wn, lane, acc);
        __syncthreads();
        writeback<3>(base, bf2, wm, wn, lane, acc);
        __syncthreads();

        // ---- stage 3: res3(128) ----
        run_stage<4, 8, 16>(base, g_F3h, g_F3l, wm, wn, lane, acc);
        __syncthreads();

        // ---- epilogue: gelu -> smem (stride 132 floats), coalesced *x -> out ----
        {
            const int mbase = wm * 32, nbase = wn * 32;
            #pragma unroll
            for (int mt = 0; mt < 2; mt++) {
                int p0 = mbase + mt*16 + (lane >> 2);
                #pragma unroll
                for (int nt = 0; nt < 4; nt++) {
                    int o = nbase + nt*8 + (lane & 3)*2;
                    float b0 = __ldg(&bf3[o]), b1 = __ldg(&bf3[o+1]);
                    #pragma unroll
                    for (int hrow = 0; hrow < 2; hrow++) {
                        float v0 = acc[mt][nt][2*hrow+0] + b0;
                        float v1 = acc[mt][nt][2*hrow+1] + b1;
                        float g0 = 0.5f * v0 * (1.0f + erff(v0 * 0.70710678118654752f));
                        float g1 = 0.5f * v1 * (1.0f + erff(v1 * 0.70710678118654752f));
                        int p = p0 + hrow*8;
                        sts32(base + ((uint32_t)o    *132 + p)*4, __float_as_uint(g0));
                        sts32(base + ((uint32_t)(o+1)*132 + p)*4, __float_as_uint(g1));
                    }
                }
            }
        }
        __syncthreads();
        for (int i = tid; i < 128*32; i += NTHR) {
            int ch = i >> 5, g4 = (i & 31) * 4;
            size_t gi = ((size_t)(b*128 + ch) << 16) + rem + g4;
            float v0, v1, v2, v3;
            lds128(v0, v1, v2, v3, base + ((uint32_t)ch*132 + g4)*4);
            float4 xv = *(const float4*)&x[gi];
            float4 o4;
            o4.x = v0 * xv.x; o4.y = v1 * xv.y; o4.z = v2 * xv.z; o4.w = v3 * xv.w;
            *(float4*)&out[gi] = o4;
        }
    }
}

// ---------------- launch ----------------
extern "C" void kernel_launch(void* const* d_in, const int* in_sizes, int n_in,
                              void* d_out, int out_size)
{
    const float* x   = (const float*)d_in[0];
    const float* wdw = (const float*)d_in[1];
    const float* bdw = (const float*)d_in[2];
    const float* wf1 = (const float*)d_in[3];
    const float* bf1 = (const float*)d_in[4];
    const float* wf2 = (const float*)d_in[5];
    const float* bf2 = (const float*)d_in[6];
    const float* wf3 = (const float*)d_in[7];
    const float* bf3 = (const float*)d_in[8];
    float* out = (float*)d_out;
    (void)in_sizes; (void)n_in; (void)out_size;

    cudaFuncSetAttribute(fused_mma, cudaFuncAttributeMaxDynamicSharedMemorySize, SMEM_REQ);

    k_prep<<<(ENT1+ENT2+ENT3 + 255)/256, 256>>>(wf1, wf2, wf3);               // 0
    k_pool2<<<(BB*CL*128*128)/256, 256>>>(x);                                 // 1
    k_pool4<<<(BB*CL*64*64)/256, 256>>>(x);                                   // 2
    k_pool8<<<(BB*CL*32*32)/256, 256>>>(x);                                   // 3
    k_dwall<<<(N_DW0+N_DW1+N_DW2+N_DW3)/256, 256>>>(x, wdw, bdw);             // 4
    fused_mma<<<1024, NTHR, SMEM_REQ>>>(x, bf1, bf2, bf3, out);               // 5
}

// round 8
// speedup vs baseline: 1.2414x; 1.2414x over previous
#include <cuda_runtime.h>
#include <cuda_fp16.h>
#include <math.h>
#include <stdint.h>

#define BB  8
#define DIM 128
#define CL  32
#define HH  256
#define WW  256

#define APITCH 136            // fp16 elems per row (pitch) of A / weight images
#define APB    (APITCH*2)     // 272 B rows: 17*16 -> ldmatrix-aligned, conflict-free

// ---------------- device scratch ----------------
__device__ float g_S0[BB*CL*HH*WW];
__device__ float g_P1[BB*CL*128*128];
__device__ float g_D1[BB*CL*128*128];
__device__ float g_P2[BB*CL*64*64];
__device__ float g_D2[BB*CL*64*64];
__device__ float g_P3[BB*CL*32*32];
__device__ float g_D3[BB*CL*32*32];

// weight images: shuffle-folded, fp16 hi/lo split, [N][APITCH]
__device__ __align__(16) __half g_W1h[64*APITCH];
__device__ __align__(16) __half g_W1l[64*APITCH];
__device__ __align__(16) __half g_W2h[96*APITCH];
__device__ __align__(16) __half g_W2l[96*APITCH];
__device__ __align__(16) __half g_W3h[128*APITCH];
__device__ __align__(16) __half g_W3l[128*APITCH];

// ---------------- smem layout (fused kernel): 102 KB -> 2 CTAs/SM ----------------
#define OFF_A  0              // 128 px rows x 272 B (fp16 activations)
#define OFF_WH 34816          // up to 128 N-rows x 272 B
#define OFF_WL 69632
#define SMEM_REQ 104448       // epilogue float buffer overlays base+0 (67584 B)

// ---------------- asm helpers ----------------
__device__ __forceinline__ uint32_t smem_u32(const void* p) {
    uint32_t a;
    asm("{ .reg .u64 t; cvta.to.shared.u64 t, %1; cvt.u32.u64 %0, t; }" : "=r"(a) : "l"(p));
    return a;
}
__device__ __forceinline__ void ldsm_x4(uint32_t r[4], uint32_t addr) {
    asm volatile("ldmatrix.sync.aligned.m8n8.x4.shared.b16 {%0,%1,%2,%3}, [%4];"
        : "=r"(r[0]), "=r"(r[1]), "=r"(r[2]), "=r"(r[3]) : "r"(addr));
}
__device__ __forceinline__ void ldsm_x2(uint32_t& r0, uint32_t& r1, uint32_t addr) {
    asm volatile("ldmatrix.sync.aligned.m8n8.x2.shared.b16 {%0,%1}, [%2];"
        : "=r"(r0), "=r"(r1) : "r"(addr));
}
__device__ __forceinline__ void mma16816h(float d[4], const uint32_t a[4], uint32_t b0, uint32_t b1) {
    asm volatile("mma.sync.aligned.m16n8k16.row.col.f32.f16.f16.f32 "
        "{%0,%1,%2,%3}, {%4,%5,%6,%7}, {%8,%9}, {%0,%1,%2,%3};"
        : "+f"(d[0]), "+f"(d[1]), "+f"(d[2]), "+f"(d[3])
        : "r"(a[0]), "r"(a[1]), "r"(a[2]), "r"(a[3]), "r"(b0), "r"(b1));
}
__device__ __forceinline__ void sts32(uint32_t addr, uint32_t v) {
    asm volatile("st.shared.b32 [%0], %1;" :: "r"(addr), "r"(v) : "memory");
}
__device__ __forceinline__ void sts128(uint32_t addr, uint4 v) {
    asm volatile("st.shared.v4.b32 [%0], {%1,%2,%3,%4};"
        :: "r"(addr), "r"(v.x), "r"(v.y), "r"(v.z), "r"(v.w) : "memory");
}
__device__ __forceinline__ void lds128(float& a, float& b, float& c, float& d, uint32_t addr) {
    asm volatile("ld.shared.v4.f32 {%0,%1,%2,%3}, [%4];"
        : "=f"(a), "=f"(b), "=f"(c), "=f"(d) : "r"(addr));
}
__device__ __forceinline__ uint16_t h16(float v) {
    return __half_as_ushort(__float2half(v));
}

// ---------------- weight prep: shuffle-fold + fp16 hi/lo split ----------------
__global__ void k_prep(const float* __restrict__ w1, const float* __restrict__ w2,
                       const float* __restrict__ w3)
{
    int t = blockIdx.x * blockDim.x + threadIdx.x;
    float w; __half *ph, *pl; int r, k;
    if (t < 64*64) {
        r = t >> 6; k = t & 63;
        w = w1[(r << 6) + ((k & 7) << 3) + (k >> 3)];
        ph = g_W1h; pl = g_W1l;
    } else if (t < 64*64 + 96*96) {
        int u = t - 64*64; r = u / 96; k = u % 96;
        w = w2[r*96 + (k % 12)*8 + k/12];
        ph = g_W2h; pl = g_W2l;
    } else if (t < 64*64 + 96*96 + 128*128) {
        int u = t - 64*64 - 96*96; r = u >> 7; k = u & 127;
        w = w3[(r << 7) + ((k & 15) << 3) + (k >> 4)];
        ph = g_W3h; pl = g_W3l;
    } else return;
    __half hb = __float2half(w);
    __half lb = __float2half(w - __half2float(hb));
    ph[r*APITCH + k] = hb;
    pl[r*APITCH + k] = lb;
}

// ---------------- pools (all 3 levels in ONE kernel) ----------------
template<int KK>
__device__ __forceinline__ void pool_one(const float* __restrict__ x, int lvl,
                                         float* __restrict__ out, int idx)
{
    const int HO = HH / KK;
    int xo = idx % HO;
    int yo = (idx / HO) % HO;
    int c  = (idx / (HO*HO)) % CL;
    int b  = idx / (HO*HO*CL);
    const float* p = x + (((size_t)b*DIM + lvl*CL + c)*HH + (size_t)yo*KK)*WW + (size_t)xo*KK;
    float m = -3.402823466e38f;
    #pragma unroll
    for (int dy = 0; dy < KK; dy++)
        #pragma unroll
        for (int dx = 0; dx < KK; dx++)
            m = fmaxf(m, p[dy*WW + dx]);
    out[idx] = m;
}
#define N_P1 (BB*CL*128*128)
#define N_P2 (BB*CL*64*64)
#define N_P3 (BB*CL*32*32)
__global__ void k_pools(const float* __restrict__ x)
{
    int idx = blockIdx.x * blockDim.x + threadIdx.x;
    if (idx < N_P1) { pool_one<2>(x, 1, g_P1, idx); return; }
    idx -= N_P1;
    if (idx < N_P2) { pool_one<4>(x, 2, g_P2, idx); return; }
    idx -= N_P2;
    if (idx < N_P3) { pool_one<8>(x, 3, g_P3, idx); return; }
}

// ---------------- depthwise 3x3 (all levels, one kernel) ----------------
__device__ __forceinline__ void dw_one(const float* __restrict__ in, float* __restrict__ out,
                                       const float* __restrict__ w_dw, const float* __restrict__ b_dw,
                                       int lvl, int S, bool from_x, int idx)
{
    int xx = idx % S;
    int yy = (idx / S) % S;
    int c  = (idx / (S*S)) % CL;
    int b  = idx / (S*S*CL);
    const float* ip = from_x ? in + ((size_t)b*DIM + lvl*CL + c) * (size_t)(S*S)
                             : in + ((size_t)b*CL + c) * (size_t)(S*S);
    const float* wp = w_dw + (lvl*CL + c) * 9;
    float acc = b_dw[lvl*CL + c];
    #pragma unroll
    for (int ky = 0; ky < 3; ky++) {
        int iy = yy + ky - 1;
        if ((unsigned)iy >= (unsigned)S) continue;
        #pragma unroll
        for (int kx = 0; kx < 3; kx++) {
            int ix = xx + kx - 1;
            if ((unsigned)ix >= (unsigned)S) continue;
            acc = fmaf(wp[ky*3 + kx], ip[iy*S + ix], acc);
        }
    }
    out[idx] = acc;
}
#define N_DW0 (BB*CL*256*256)
#define N_DW1 (BB*CL*128*128)
#define N_DW2 (BB*CL*64*64)
#define N_DW3 (BB*CL*32*32)
__global__ void k_dwall(const float* __restrict__ x, const float* __restrict__ w,
                        const float* __restrict__ b)
{
    int idx = blockIdx.x * blockDim.x + threadIdx.x;
    if (idx < N_DW0) { dw_one(x, g_S0, w, b, 0, 256, true, idx); return; }
    idx -= N_DW0;
    if (idx < N_DW1) { dw_one(g_P1, g_D1, w, b, 1, 128, false, idx); return; }
    idx -= N_DW1;
    if (idx < N_DW2) { dw_one(g_P2, g_D2, w, b, 2, 64, false, idx); return; }
    idx -= N_DW2;
    if (idx < N_DW3) { dw_one(g_P3, g_D3, w, b, 3, 32, false, idx); return; }
}

// ---------------- full-stage W loader: gmem (L2-hot) -> smem ----------------
// copies bytes [0, kbytes) of each of N rows, pitch APB on both sides
__device__ __forceinline__ void load_w(uint32_t base,
                                       const __half* __restrict__ gh,
                                       const __half* __restrict__ gl,
                                       int N, int kbytes, int tid)
{
    int chunks = kbytes >> 4;
    int total = N * chunks;
    for (int i = tid; i < total; i += 512) {
        int r = i / chunks, c = (i - r*chunks) << 4;
        uint4 vh = *(const uint4*)((const char*)gh + r*APB + c);
        uint4 vl = *(const uint4*)((const char*)gl + r*APB + c);
        uint32_t d = base + (uint32_t)r*APB + c;
        sts128(d + OFF_WH, vh);
        sts128(d + OFF_WL, vl);
    }
}

// ---------------- GEMM stage (warp-level mma, fp16 2-term) ----------------
// 16 warps: grid 4(M) x 4(N). Warp tile: 32 px x NT*8 out ch. KT k-steps of 16.
template<int NT, int KT>
__device__ __forceinline__ void run_stage(uint32_t base, int wm, int wn, int lane,
                                          float acc[2][4][4])
{
    #pragma unroll
    for (int mt = 0; mt < 2; mt++)
        #pragma unroll
        for (int nt = 0; nt < NT; nt++)
            #pragma unroll
            for (int i = 0; i < 4; i++) acc[mt][nt][i] = 0.0f;

    const int mbase = wm * 32;
    const int nbase = wn * NT * 8;
    const uint32_t a_off = (uint32_t)(mbase + (lane & 15)) * APB + ((lane >> 4) << 4);
    const uint32_t b_off = (uint32_t)(nbase + (lane & 7)) * APB + (((lane >> 3) & 1) << 4);
    const uint32_t A  = base + OFF_A  + a_off;
    const uint32_t WH = base + OFF_WH + b_off;
    const uint32_t WL = base + OFF_WL + b_off;

    #pragma unroll
    for (int kt = 0; kt < KT; kt++) {
        uint32_t ah[2][4];
        #pragma unroll
        for (int mt = 0; mt < 2; mt++)
            ldsm_x4(ah[mt], A + mt*16*APB + kt*32);
        #pragma unroll
        for (int nt = 0; nt < NT; nt++) {
            uint32_t bh0, bh1, bl0, bl1;
            ldsm_x2(bh0, bh1, WH + nt*8*APB + kt*32);
            ldsm_x2(bl0, bl1, WL + nt*8*APB + kt*32);
            #pragma unroll
            for (int mt = 0; mt < 2; mt++) {
                mma16816h(acc[mt][nt], ah[mt], bh0, bh1);
                mma16816h(acc[mt][nt], ah[mt], bl0, bl1);
            }
        }
    }
}

// write acc (+bias) back into A as fp16, channels [nbase, nbase+NT*8)
template<int NT>
__device__ __forceinline__ void writeback(uint32_t base, const float* __restrict__ bias,
                                          int wm, int wn, int lane, float acc[2][4][4])
{
    const int mbase = wm * 32;
    const int nbase = wn * NT * 8;
    #pragma unroll
    for (int mt = 0; mt < 2; mt++) {
        int p0 = mbase + mt*16 + (lane >> 2);
        #pragma unroll
        for (int nt = 0; nt < NT; nt++) {
            int o = nbase + nt*8 + (lane & 3)*2;
            float b0 = __ldg(&bias[o]), b1 = __ldg(&bias[o+1]);
            uint32_t addr = base + OFF_A + (uint32_t)p0*APB + o*2;
            sts32(addr, (uint32_t)h16(acc[mt][nt][0] + b0)
                      | ((uint32_t)h16(acc[mt][nt][1] + b1) << 16));
            sts32(addr + 8*APB, (uint32_t)h16(acc[mt][nt][2] + b0)
                              | ((uint32_t)h16(acc[mt][nt][3] + b1) << 16));
        }
    }
}

// ---------------- fused kernel: 512 threads, 16 warps, 2 CTAs/SM ----------------
#define TPC 4
#define NTHR 512
__global__ __launch_bounds__(NTHR, 2)
void fused_mma(const float* __restrict__ x,
               const float* __restrict__ bf1, const float* __restrict__ bf2,
               const float* __restrict__ bf3, float* __restrict__ out)
{
    extern __shared__ __align__(16) unsigned char sm[];
    const uint32_t base = smem_u32(sm);
    const int tid = threadIdx.x;
    const int lane = tid & 31, wid = tid >> 5;
    const int wm = wid >> 2, wn = wid & 3;

    float acc[2][4][4];

    for (int t = 0; t < TPC; t++) {
        int tile = blockIdx.x * TPC + t;
        int b = tile >> 9;
        int rem = (tile & 511) * 128;

        __syncthreads();   // S0: prev-tile epilogue reads done; smem free

        // ---- build A (128 px x 128 ch, fp16, 2 ch per sts32) + load stage-1 W ----
        for (int i = tid; i < 128*64; i += NTHR) {
            int chp = i >> 7, p = i & 127;
            int ch = chp*2;
            int r = rem + p;
            int y = r >> 8, xx = r & 255;
            float v0, v1;
            if (ch < 32) {
                const float* s = &g_S0[((b*32 + ch) << 16) + r];
                v0 = s[0]; v1 = s[1 << 16];
            } else if (ch < 64) {
                const float* s = &g_D1[(b*32 + ch-32)*16384 + (y>>1)*128 + (xx>>1)];
                v0 = s[0]; v1 = s[16384];
            } else if (ch < 96) {
                const float* s = &g_D2[(b*32 + ch-64)*4096 + (y>>2)*64 + (xx>>2)];
                v0 = s[0]; v1 = s[4096];
            } else {
                const float* s = &g_D3[(b*32 + ch-96)*1024 + (y>>3)*32 + (xx>>3)];
                v0 = s[0]; v1 = s[1024];
            }
            sts32(base + OFF_A + (uint32_t)p*APB + ch*2,
                  (uint32_t)h16(v0) | ((uint32_t)h16(v1) << 16));
        }
        load_w(base, g_W1h, g_W1l, 64, 128, tid);
        __syncthreads();   // S1

        // ---- stage 1: res1(64), K=64 ----
        run_stage<2, 4>(base, wm, wn, lane, acc);
        __syncthreads();   // S2: W reads + A reads done
        writeback<2>(base, bf1, wm, wn, lane, acc);
        load_w(base, g_W2h, g_W2l, 96, 192, tid);
        __syncthreads();   // S3

        // ---- stage 2: res2(96), K=96 ----
        run_stage<3, 6>(base, wm, wn, lane, acc);
        __syncthreads();   // S4
        writeback<3>(base, bf2, wm, wn, lane, acc);
        load_w(base, g_W3h, g_W3l, 128, 256, tid);
        __syncthreads();   // S5

        // ---- stage 3: res3(128), K=128 ----
        run_stage<4, 8>(base, wm, wn, lane, acc);
        __syncthreads();   // S6: all smem reads done; epilogue overlays

        // ---- epilogue: gelu -> smem floats (stride 132), coalesced *x -> out ----
        {
            const int mbase = wm * 32, nbase = wn * 32;
            #pragma unroll
            for (int mt = 0; mt < 2; mt++) {
                int p0 = mbase + mt*16 + (lane >> 2);
                #pragma unroll
                for (int nt = 0; nt < 4; nt++) {
                    int o = nbase + nt*8 + (lane & 3)*2;
                    float b0 = __ldg(&bf3[o]), b1 = __ldg(&bf3[o+1]);
                    #pragma unroll
                    for (int hrow = 0; hrow < 2; hrow++) {
                        float v0 = acc[mt][nt][2*hrow+0] + b0;
                        float v1 = acc[mt][nt][2*hrow+1] + b1;
                        float g0 = 0.5f * v0 * (1.0f + erff(v0 * 0.70710678118654752f));
                        float g1 = 0.5f * v1 * (1.0f + erff(v1 * 0.70710678118654752f));
                        int p = p0 + hrow*8;
                        sts32(base + ((uint32_t)o    *132 + p)*4, __float_as_uint(g0));
                        sts32(base + ((uint32_t)(o+1)*132 + p)*4, __float_as_uint(g1));
                    }
                }
            }
        }
        __syncthreads();   // S7
        for (int i = tid; i < 128*32; i += NTHR) {
            int ch = i >> 5, g4 = (i & 31) * 4;
            size_t gi = ((size_t)(b*128 + ch) << 16) + rem + g4;
            float v0, v1, v2, v3;
            lds128(v0, v1, v2, v3, base + ((uint32_t)ch*132 + g4)*4);
            float4 xv = *(const float4*)&x[gi];
            float4 o4;
            o4.x = v0 * xv.x; o4.y = v1 * xv.y; o4.z = v2 * xv.z; o4.w = v3 * xv.w;
            *(float4*)&out[gi] = o4;
        }
    }
}

// ---------------- launch ----------------
extern "C" void kernel_launch(void* const* d_in, const int* in_sizes, int n_in,
                              void* d_out, int out_size)
{
    const float* x   = (const float*)d_in[0];
    const float* wdw = (const float*)d_in[1];
    const float* bdw = (const float*)d_in[2];
    const float* wf1 = (const float*)d_in[3];
    const float* bf1 = (const float*)d_in[4];
    const float* wf2 = (const float*)d_in[5];
    const float* bf2 = (const float*)d_in[6];
    const float* wf3 = (const float*)d_in[7];
    const float* bf3 = (const float*)d_in[8];
    float* out = (float*)d_out;
    (void)in_sizes; (void)n_in; (void)out_size;

    cudaFuncSetAttribute(fused_mma, cudaFuncAttributeMaxDynamicSharedMemorySize, SMEM_REQ);

    k_prep<<<(64*64 + 96*96 + 128*128 + 255)/256, 256>>>(wf1, wf2, wf3);      // 0
    k_pools<<<(N_P1+N_P2+N_P3 + 255)/256, 256>>>(x);                          // 1
    k_dwall<<<(N_DW0+N_DW1+N_DW2+N_DW3)/256, 256>>>(x, wdw, bdw);             // 2
    fused_mma<<<1024, NTHR, SMEM_REQ>>>(x, bf1, bf2, bf3, out);               // 3
}

// round 9
// speedup vs baseline: 1.3790x; 1.1109x over previous
#include <cuda_runtime.h>
#include <cuda_fp16.h>
#include <math.h>
#include <stdint.h>

#define BB  8
#define DIM 128
#define CL  32
#define HH  256
#define WW  256

#define APITCH 136            // fp16 elems per row (pitch) of A / weight images
#define APB    (APITCH*2)     // 272 B rows: 17*16 -> ldmatrix-aligned, conflict-free
#define EPITCH 260            // epilogue float pitch (conflict-free)

// ---------------- device scratch ----------------
__device__ float g_S0[BB*CL*HH*WW];
__device__ float g_P1[BB*CL*128*128];
__device__ float g_D1[BB*CL*128*128];
__device__ float g_P2[BB*CL*64*64];
__device__ float g_D2[BB*CL*64*64];
__device__ float g_P3[BB*CL*32*32];
__device__ float g_D3[BB*CL*32*32];

// weight images: shuffle-folded, fp16 hi/lo split, [N][APITCH]
__device__ __align__(16) __half g_W1h[64*APITCH];
__device__ __align__(16) __half g_W1l[64*APITCH];
__device__ __align__(16) __half g_W2h[96*APITCH];
__device__ __align__(16) __half g_W2l[96*APITCH];
__device__ __align__(16) __half g_W3h[128*APITCH];
__device__ __align__(16) __half g_W3l[128*APITCH];

// ---------------- smem layout: A(256x272) + all W resident = 221 KB ----------------
#define OFF_A   0
#define OFF_W1H 69632
#define OFF_W1L 87040
#define OFF_W2H 104448
#define OFF_W2L 130560
#define OFF_W3H 156672
#define OFF_W3L 191488
#define SMEM_REQ 226304

// ---------------- asm helpers ----------------
__device__ __forceinline__ uint32_t smem_u32(const void* p) {
    uint32_t a;
    asm("{ .reg .u64 t; cvta.to.shared.u64 t, %1; cvt.u32.u64 %0, t; }" : "=r"(a) : "l"(p));
    return a;
}
__device__ __forceinline__ void ldsm_x4(uint32_t r[4], uint32_t addr) {
    asm volatile("ldmatrix.sync.aligned.m8n8.x4.shared.b16 {%0,%1,%2,%3}, [%4];"
        : "=r"(r[0]), "=r"(r[1]), "=r"(r[2]), "=r"(r[3]) : "r"(addr));
}
__device__ __forceinline__ void mma16816h(float d[4], const uint32_t a[4], uint32_t b0, uint32_t b1) {
    asm volatile("mma.sync.aligned.m16n8k16.row.col.f32.f16.f16.f32 "
        "{%0,%1,%2,%3}, {%4,%5,%6,%7}, {%8,%9}, {%0,%1,%2,%3};"
        : "+f"(d[0]), "+f"(d[1]), "+f"(d[2]), "+f"(d[3])
        : "r"(a[0]), "r"(a[1]), "r"(a[2]), "r"(a[3]), "r"(b0), "r"(b1));
}
__device__ __forceinline__ void sts32(uint32_t addr, uint32_t v) {
    asm volatile("st.shared.b32 [%0], %1;" :: "r"(addr), "r"(v) : "memory");
}
__device__ __forceinline__ void sts128(uint32_t addr, uint4 v) {
    asm volatile("st.shared.v4.b32 [%0], {%1,%2,%3,%4};"
        :: "r"(addr), "r"(v.x), "r"(v.y), "r"(v.z), "r"(v.w) : "memory");
}
__device__ __forceinline__ void lds128(float& a, float& b, float& c, float& d, uint32_t addr) {
    asm volatile("ld.shared.v4.f32 {%0,%1,%2,%3}, [%4];"
        : "=f"(a), "=f"(b), "=f"(c), "=f"(d) : "f"(0.0f), "r"(addr));
}
__device__ __forceinline__ void lds128v(float& a, float& b, float& c, float& d, uint32_t addr) {
    asm volatile("ld.shared.v4.f32 {%0,%1,%2,%3}, [%4];"
        : "=f"(a), "=f"(b), "=f"(c), "=f"(d) : "r"(addr));
}
__device__ __forceinline__ uint16_t h16(float v) {
    return __half_as_ushort(__float2half(v));
}
__device__ __forceinline__ uint32_t pack2(uint16_t a, uint16_t b) {
    return (uint32_t)a | ((uint32_t)b << 16);
}

// ---------------- weight prep: shuffle-fold + fp16 hi/lo split ----------------
__global__ void k_prep(const float* __restrict__ w1, const float* __restrict__ w2,
                       const float* __restrict__ w3)
{
    int t = blockIdx.x * blockDim.x + threadIdx.x;
    float w; __half *ph, *pl; int r, k;
    if (t < 64*64) {
        r = t >> 6; k = t & 63;
        w = w1[(r << 6) + ((k & 7) << 3) + (k >> 3)];
        ph = g_W1h; pl = g_W1l;
    } else if (t < 64*64 + 96*96) {
        int u = t - 64*64; r = u / 96; k = u % 96;
        w = w2[r*96 + (k % 12)*8 + k/12];
        ph = g_W2h; pl = g_W2l;
    } else if (t < 64*64 + 96*96 + 128*128) {
        int u = t - 64*64 - 96*96; r = u >> 7; k = u & 127;
        w = w3[(r << 7) + ((k & 15) << 3) + (k >> 4)];
        ph = g_W3h; pl = g_W3l;
    } else return;
    __half hb = __float2half(w);
    __half lb = __float2half(w - __half2float(hb));
    ph[r*APITCH + k] = hb;
    pl[r*APITCH + k] = lb;
}

// ---------------- pools (separate kernels — measured faster than merged) ----------------
template<int KK>
__device__ __forceinline__ void pool_impl(const float* __restrict__ x, int lvl,
                                          float* __restrict__ out)
{
    const int HO = HH / KK;
    int idx = blockIdx.x * blockDim.x + threadIdx.x;
    if (idx >= BB*CL*HO*HO) return;
    int xo = idx % HO;
    int yo = (idx / HO) % HO;
    int c  = (idx / (HO*HO)) % CL;
    int b  = idx / (HO*HO*CL);
    const float* p = x + (((size_t)b*DIM + lvl*CL + c)*HH + (size_t)yo*KK)*WW + (size_t)xo*KK;
    float m = -3.402823466e38f;
    #pragma unroll
    for (int dy = 0; dy < KK; dy++)
        #pragma unroll
        for (int dx = 0; dx < KK; dx++)
            m = fmaxf(m, p[dy*WW + dx]);
    out[idx] = m;
}
__global__ void k_pool2(const float* __restrict__ x){ pool_impl<2>(x, 1, g_P1); }
__global__ void k_pool4(const float* __restrict__ x){ pool_impl<4>(x, 2, g_P2); }
__global__ void k_pool8(const float* __restrict__ x){ pool_impl<8>(x, 3, g_P3); }

// ---------------- depthwise 3x3 (all levels, one kernel) ----------------
__device__ __forceinline__ void dw_one(const float* __restrict__ in, float* __restrict__ out,
                                       const float* __restrict__ w_dw, const float* __restrict__ b_dw,
                                       int lvl, int S, bool from_x, int idx)
{
    int xx = idx % S;
    int yy = (idx / S) % S;
    int c  = (idx / (S*S)) % CL;
    int b  = idx / (S*S*CL);
    const float* ip = from_x ? in + ((size_t)b*DIM + lvl*CL + c) * (size_t)(S*S)
                             : in + ((size_t)b*CL + c) * (size_t)(S*S);
    const float* wp = w_dw + (lvl*CL + c) * 9;
    float acc = b_dw[lvl*CL + c];
    #pragma unroll
    for (int ky = 0; ky < 3; ky++) {
        int iy = yy + ky - 1;
        if ((unsigned)iy >= (unsigned)S) continue;
        #pragma unroll
        for (int kx = 0; kx < 3; kx++) {
            int ix = xx + kx - 1;
            if ((unsigned)ix >= (unsigned)S) continue;
            acc = fmaf(wp[ky*3 + kx], ip[iy*S + ix], acc);
        }
    }
    out[idx] = acc;
}
#define N_DW0 (BB*CL*256*256)
#define N_DW1 (BB*CL*128*128)
#define N_DW2 (BB*CL*64*64)
#define N_DW3 (BB*CL*32*32)
__global__ void k_dwall(const float* __restrict__ x, const float* __restrict__ w,
                        const float* __restrict__ b)
{
    int idx = blockIdx.x * blockDim.x + threadIdx.x;
    if (idx < N_DW0) { dw_one(x, g_S0, w, b, 0, 256, true, idx); return; }
    idx -= N_DW0;
    if (idx < N_DW1) { dw_one(g_P1, g_D1, w, b, 1, 128, false, idx); return; }
    idx -= N_DW1;
    if (idx < N_DW2) { dw_one(g_P2, g_D2, w, b, 2, 64, false, idx); return; }
    idx -= N_DW2;
    if (idx < N_DW3) { dw_one(g_P3, g_D3, w, b, 3, 32, false, idx); return; }
}

// ---------------- D -> A fragment conversion (register-local) ----------------
// A k-tile j of next stage = D tiles g0=2j, g0+1 with bias, fp16-packed.
__device__ __forceinline__ void d2a(const float d[][4], int g0, const float* __restrict__ bias,
                                    int lane, uint32_t a[4])
{
    int c0 = 8*g0 + (lane & 3)*2;
    float b00 = __ldg(bias + c0),     b01 = __ldg(bias + c0 + 1);
    float b10 = __ldg(bias + c0 + 8), b11 = __ldg(bias + c0 + 9);
    a[0] = pack2(h16(d[g0][0] + b00),   h16(d[g0][1] + b01));
    a[1] = pack2(h16(d[g0][2] + b00),   h16(d[g0][3] + b01));
    a[2] = pack2(h16(d[g0+1][0] + b10), h16(d[g0+1][1] + b11));
    a[3] = pack2(h16(d[g0+1][2] + b10), h16(d[g0+1][3] + b11));
}

// ---------------- fused kernel: warp-local chain, 512 thr, 16 warps, 1 CTA/SM ----------------
#define TPC 2
#define NTHR 512
__global__ __launch_bounds__(NTHR, 1)
void fused_mma(const float* __restrict__ x,
               const float* __restrict__ bf1, const float* __restrict__ bf2,
               const float* __restrict__ bf3, float* __restrict__ out)
{
    extern __shared__ __align__(16) unsigned char sm[];
    const uint32_t base = smem_u32(sm);
    const int tid = threadIdx.x;
    const int lane = tid & 31, wid = tid >> 5;   // wid 0..15, owns pixels [wid*16, +16)

    // ---- load ALL weight images into smem once ----
    {
        const __half* gs[6] = { g_W1h, g_W1l, g_W2h, g_W2l, g_W3h, g_W3l };
        const int off[6] = { OFF_W1H, OFF_W1L, OFF_W2H, OFF_W2L, OFF_W3H, OFF_W3L };
        const int sz[6]  = { 17408, 17408, 26112, 26112, 34816, 34816 };
        #pragma unroll
        for (int a = 0; a < 6; a++) {
            const uint4* s4 = (const uint4*)gs[a];
            for (int i = tid; i < sz[a]/16; i += NTHR)
                sts128(base + off[a] + i*16, s4[i]);
        }
    }

    // per-warp constant addresses
    const uint32_t Abase = base + OFF_A + (uint32_t)(wid*16 + (lane & 15))*APB + ((lane >> 4) << 4);
    const uint32_t wlo   = (uint32_t)(lane & 7)*APB + (((lane >> 3) & 1) << 4);
    const uint32_t W1sel = base + ((lane < 16) ? OFF_W1H : OFF_W1L) + wlo;
    const uint32_t W2sel = base + ((lane < 16) ? OFF_W2H : OFF_W2L) + wlo;
    const uint32_t W3sel = base + ((lane < 16) ? OFF_W3H : OFF_W3L) + wlo;

    float acc[16][4];
    uint32_t areg[6][4];

    for (int t = 0; t < TPC; t++) {
        int tile = blockIdx.x * TPC + t;
        int b = tile >> 8;                // 256 tiles (rows) per image
        int rem = (tile & 255) * 256;     // pixel base = one full image row

        __syncthreads();   // S0: prev-tile epilogue reads done

        // ---- build A (256 px x 128 ch, fp16, 2 ch per sts32) ----
        for (int i = tid; i < 256*64; i += NTHR) {
            int chp = i >> 8, p = i & 255;
            int ch = chp*2;
            int r = rem + p;
            int y = r >> 8, xx = r & 255;
            float v0, v1;
            if (ch < 32) {
                const float* s = &g_S0[((b*32 + ch) << 16) + r];
                v0 = s[0]; v1 = s[1 << 16];
            } else if (ch < 64) {
                const float* s = &g_D1[(b*32 + ch-32)*16384 + (y>>1)*128 + (xx>>1)];
                v0 = s[0]; v1 = s[16384];
            } else if (ch < 96) {
                const float* s = &g_D2[(b*32 + ch-64)*4096 + (y>>2)*64 + (xx>>2)];
                v0 = s[0]; v1 = s[4096];
            } else {
                const float* s = &g_D3[(b*32 + ch-96)*1024 + (y>>3)*32 + (xx>>3)];
                v0 = s[0]; v1 = s[1024];
            }
            sts32(base + OFF_A + (uint32_t)p*APB + ch*2, pack2(h16(v0), h16(v1)));
        }
        __syncthreads();   // S1: A (and W on first tile) ready

        // ---- stage 1: res1(64) = W1 @ A[0:64]  (KT=4, NT=8) ----
        #pragma unroll
        for (int n = 0; n < 8; n++)
            #pragma unroll
            for (int i = 0; i < 4; i++) acc[n][i] = 0.0f;
        #pragma unroll
        for (int kt = 0; kt < 4; kt++) {
            uint32_t a[4];
            ldsm_x4(a, Abase + kt*32);
            #pragma unroll
            for (int nt = 0; nt < 8; nt++) {
                uint32_t f[4];
                ldsm_x4(f, W1sel + (uint32_t)nt*(8*APB) + kt*32);
                mma16816h(acc[nt], a, f[0], f[1]);
                mma16816h(acc[nt], a, f[2], f[3]);
            }
        }
        #pragma unroll
        for (int j = 0; j < 4; j++) d2a(acc, 2*j, bf1, lane, areg[j]);

        // ---- stage 2: res2(96) = W2 @ [res1; s2]  (KT=6, NT=12) ----
        #pragma unroll
        for (int n = 0; n < 12; n++)
            #pragma unroll
            for (int i = 0; i < 4; i++) acc[n][i] = 0.0f;
        #pragma unroll
        for (int kt = 0; kt < 6; kt++) {
            uint32_t a[4];
            if (kt < 4) { a[0]=areg[kt][0]; a[1]=areg[kt][1]; a[2]=areg[kt][2]; a[3]=areg[kt][3]; }
            else ldsm_x4(a, Abase + kt*32);
            #pragma unroll
            for (int nt = 0; nt < 12; nt++) {
                uint32_t f[4];
                ldsm_x4(f, W2sel + (uint32_t)nt*(8*APB) + kt*32);
                mma16816h(acc[nt], a, f[0], f[1]);
                mma16816h(acc[nt], a, f[2], f[3]);
            }
        }
        #pragma unroll
        for (int j = 0; j < 6; j++) d2a(acc, 2*j, bf2, lane, areg[j]);

        // ---- stage 3: res3(128) = W3 @ [res2; s3]  (KT=8, NT=16) ----
        #pragma unroll
        for (int n = 0; n < 16; n++)
            #pragma unroll
            for (int i = 0; i < 4; i++) acc[n][i] = 0.0f;
        #pragma unroll
        for (int kt = 0; kt < 8; kt++) {
            uint32_t a[4];
            if (kt < 6) { a[0]=areg[kt][0]; a[1]=areg[kt][1]; a[2]=areg[kt][2]; a[3]=areg[kt][3]; }
            else ldsm_x4(a, Abase + kt*32);
            #pragma unroll
            for (int nt = 0; nt < 16; nt++) {
                uint32_t f[4];
                ldsm_x4(f, W3sel + (uint32_t)nt*(8*APB) + kt*32);
                mma16816h(acc[nt], a, f[0], f[1]);
                mma16816h(acc[nt], a, f[2], f[3]);
            }
        }
        __syncthreads();   // S2: all A-region reads done; epilogue overlays it

        // ---- epilogue: two 64-channel halves via smem transpose ----
        #pragma unroll
        for (int h = 0; h < 2; h++) {
            #pragma unroll
            for (int ntl = 0; ntl < 8; ntl++) {
                int nt = h*8 + ntl;
                int ol = ntl*8 + (lane & 3)*2;       // buffer row (0..63)
                int c  = h*64 + ol;                   // global channel
                float b0 = __ldg(&bf3[c]), b1 = __ldg(&bf3[c+1]);
                int p0 = wid*16 + (lane >> 2);
                #pragma unroll
                for (int hrow = 0; hrow < 2; hrow++) {
                    float v0 = acc[nt][2*hrow+0] + b0;
                    float v1 = acc[nt][2*hrow+1] + b1;
                    float g0 = 0.5f * v0 * (1.0f + erff(v0 * 0.70710678118654752f));
                    float g1 = 0.5f * v1 * (1.0f + erff(v1 * 0.70710678118654752f));
                    int p = p0 + hrow*8;
                    sts32(base + ((uint32_t)ol    *EPITCH + p)*4, __float_as_uint(g0));
                    sts32(base + ((uint32_t)(ol+1)*EPITCH + p)*4, __float_as_uint(g1));
                }
            }
            __syncthreads();
            for (int i = tid; i < 64*64; i += NTHR) {
                int chl = i >> 6, g4 = (i & 63)*4;
                int ch = h*64 + chl;
                size_t gi = ((size_t)(b*128 + ch) << 16) + rem + g4;
                float v0, v1, v2, v3;
                lds128v(v0, v1, v2, v3, base + ((uint32_t)chl*EPITCH + g4)*4);
                float4 xv = *(const float4*)&x[gi];
                float4 o4;
                o4.x = v0 * xv.x; o4.y = v1 * xv.y; o4.z = v2 * xv.z; o4.w = v3 * xv.w;
                *(float4*)&out[gi] = o4;
            }
            __syncthreads();
        }
    }
}

// ---------------- launch ----------------
extern "C" void kernel_launch(void* const* d_in, const int* in_sizes, int n_in,
                              void* d_out, int out_size)
{
    const float* x   = (const float*)d_in[0];
    const float* wdw = (const float*)d_in[1];
    const float* bdw = (const float*)d_in[2];
    const float* wf1 = (const float*)d_in[3];
    const float* bf1 = (const float*)d_in[4];
    const float* wf2 = (const float*)d_in[5];
    const float* bf2 = (const float*)d_in[6];
    const float* wf3 = (const float*)d_in[7];
    const float* bf3 = (const float*)d_in[8];
    float* out = (float*)d_out;
    (void)in_sizes; (void)n_in; (void)out_size;

    cudaFuncSetAttribute(fused_mma, cudaFuncAttributeMaxDynamicSharedMemorySize, SMEM_REQ);

    k_prep<<<(64*64 + 96*96 + 128*128 + 255)/256, 256>>>(wf1, wf2, wf3);      // 0
    k_pool2<<<(BB*CL*128*128)/256, 256>>>(x);                                  // 1
    k_pool4<<<(BB*CL*64*64)/256, 256>>>(x);                                    // 2
    k_pool8<<<(BB*CL*32*32)/256, 256>>>(x);                                    // 3
    k_dwall<<<(N_DW0+N_DW1+N_DW2+N_DW3)/256, 256>>>(x, wdw, bdw);              // 4
    fused_mma<<<1024, NTHR, SMEM_REQ>>>(x, bf1, bf2, bf3, out);                // 5
}

// round 10
// speedup vs baseline: 1.6244x; 1.1779x over previous
#include <cuda_runtime.h>
#include <cuda_fp16.h>
#include <math.h>
#include <stdint.h>

#define BB  8
#define DIM 128
#define CL  32
#define HH  256
#define WW  256

#define APITCH 136            // fp16 elems per row (pitch) of A / weight images
#define APB    (APITCH*2)     // 272 B rows: 17*16 -> ldmatrix-aligned, conflict-free
#define EPITCH 132            // epilogue float pitch (128+4, conflict-free)

// ---------------- device scratch ----------------
__device__ float g_S0[BB*CL*HH*WW];
__device__ float g_P1[BB*CL*128*128];
__device__ float g_D1[BB*CL*128*128];
__device__ float g_P2[BB*CL*64*64];
__device__ float g_D2[BB*CL*64*64];
__device__ float g_P3[BB*CL*32*32];
__device__ float g_D3[BB*CL*32*32];

// weight images: shuffle-folded, single fp16, [N][APITCH]
__device__ __align__(16) __half g_W1[64*APITCH];
__device__ __align__(16) __half g_W2[96*APITCH];
__device__ __align__(16) __half g_W3[128*APITCH];

// ---------------- smem layout: A(128x272) + W1+W2+W3 = 110.5 KB -> 2 CTAs/SM ----------------
#define OFF_A   0
#define OFF_W1  34816
#define OFF_W2  52224
#define OFF_W3  78336
#define SMEM_REQ 113152

// ---------------- asm helpers ----------------
__device__ __forceinline__ uint32_t smem_u32(const void* p) {
    uint32_t a;
    asm("{ .reg .u64 t; cvta.to.shared.u64 t, %1; cvt.u32.u64 %0, t; }" : "=r"(a) : "l"(p));
    return a;
}
__device__ __forceinline__ void ldsm_x4(uint32_t r[4], uint32_t addr) {
    asm volatile("ldmatrix.sync.aligned.m8n8.x4.shared.b16 {%0,%1,%2,%3}, [%4];"
        : "=r"(r[0]), "=r"(r[1]), "=r"(r[2]), "=r"(r[3]) : "r"(addr));
}
__device__ __forceinline__ void mma16816h(float d[4], const uint32_t a[4], uint32_t b0, uint32_t b1) {
    asm volatile("mma.sync.aligned.m16n8k16.row.col.f32.f16.f16.f32 "
        "{%0,%1,%2,%3}, {%4,%5,%6,%7}, {%8,%9}, {%0,%1,%2,%3};"
        : "+f"(d[0]), "+f"(d[1]), "+f"(d[2]), "+f"(d[3])
        : "r"(a[0]), "r"(a[1]), "r"(a[2]), "r"(a[3]), "r"(b0), "r"(b1));
}
__device__ __forceinline__ void sts32(uint32_t addr, uint32_t v) {
    asm volatile("st.shared.b32 [%0], %1;" :: "r"(addr), "r"(v) : "memory");
}
__device__ __forceinline__ void sts128(uint32_t addr, uint4 v) {
    asm volatile("st.shared.v4.b32 [%0], {%1,%2,%3,%4};"
        :: "r"(addr), "r"(v.x), "r"(v.y), "r"(v.z), "r"(v.w) : "memory");
}
__device__ __forceinline__ void lds128v(float& a, float& b, float& c, float& d, uint32_t addr) {
    asm volatile("ld.shared.v4.f32 {%0,%1,%2,%3}, [%4];"
        : "=f"(a), "=f"(b), "=f"(c), "=f"(d) : "r"(addr));
}
__device__ __forceinline__ uint16_t h16(float v) {
    return __half_as_ushort(__float2half(v));
}
__device__ __forceinline__ uint32_t pack2(uint16_t a, uint16_t b) {
    return (uint32_t)a | ((uint32_t)b << 16);
}

// ---------------- weight prep: shuffle-fold + fp16 ----------------
__global__ void k_prep(const float* __restrict__ w1, const float* __restrict__ w2,
                       const float* __restrict__ w3)
{
    int t = blockIdx.x * blockDim.x + threadIdx.x;
    float w; __half *ph; int r, k;
    if (t < 64*64) {
        r = t >> 6; k = t & 63;
        w = w1[(r << 6) + ((k & 7) << 3) + (k >> 3)];
        ph = g_W1;
    } else if (t < 64*64 + 96*96) {
        int u = t - 64*64; r = u / 96; k = u % 96;
        w = w2[r*96 + (k % 12)*8 + k/12];
        ph = g_W2;
    } else if (t < 64*64 + 96*96 + 128*128) {
        int u = t - 64*64 - 96*96; r = u >> 7; k = u & 127;
        w = w3[(r << 7) + ((k & 15) << 3) + (k >> 4)];
        ph = g_W3;
    } else return;
    ph[r*APITCH + k] = __float2half(w);
}

// ---------------- pools (separate kernels — measured faster than merged) ----------------
template<int KK>
__device__ __forceinline__ void pool_impl(const float* __restrict__ x, int lvl,
                                          float* __restrict__ out)
{
    const int HO = HH / KK;
    int idx = blockIdx.x * blockDim.x + threadIdx.x;
    if (idx >= BB*CL*HO*HO) return;
    int xo = idx % HO;
    int yo = (idx / HO) % HO;
    int c  = (idx / (HO*HO)) % CL;
    int b  = idx / (HO*HO*CL);
    const float* p = x + (((size_t)b*DIM + lvl*CL + c)*HH + (size_t)yo*KK)*WW + (size_t)xo*KK;
    float m = -3.402823466e38f;
    #pragma unroll
    for (int dy = 0; dy < KK; dy++)
        #pragma unroll
        for (int dx = 0; dx < KK; dx++)
            m = fmaxf(m, p[dy*WW + dx]);
    out[idx] = m;
}
__global__ void k_pool2(const float* __restrict__ x){ pool_impl<2>(x, 1, g_P1); }
__global__ void k_pool4(const float* __restrict__ x){ pool_impl<4>(x, 2, g_P2); }
__global__ void k_pool8(const float* __restrict__ x){ pool_impl<8>(x, 3, g_P3); }

// ---------------- depthwise 3x3 (all levels, one kernel) ----------------
__device__ __forceinline__ void dw_one(const float* __restrict__ in, float* __restrict__ out,
                                       const float* __restrict__ w_dw, const float* __restrict__ b_dw,
                                       int lvl, int S, bool from_x, int idx)
{
    int xx = idx % S;
    int yy = (idx / S) % S;
    int c  = (idx / (S*S)) % CL;
    int b  = idx / (S*S*CL);
    const float* ip = from_x ? in + ((size_t)b*DIM + lvl*CL + c) * (size_t)(S*S)
                             : in + ((size_t)b*CL + c) * (size_t)(S*S);
    const float* wp = w_dw + (lvl*CL + c) * 9;
    float acc = b_dw[lvl*CL + c];
    #pragma unroll
    for (int ky = 0; ky < 3; ky++) {
        int iy = yy + ky - 1;
        if ((unsigned)iy >= (unsigned)S) continue;
        #pragma unroll
        for (int kx = 0; kx < 3; kx++) {
            int ix = xx + kx - 1;
            if ((unsigned)ix >= (unsigned)S) continue;
            acc = fmaf(wp[ky*3 + kx], ip[iy*S + ix], acc);
        }
    }
    out[idx] = acc;
}
#define N_DW0 (BB*CL*256*256)
#define N_DW1 (BB*CL*128*128)
#define N_DW2 (BB*CL*64*64)
#define N_DW3 (BB*CL*32*32)
__global__ void k_dwall(const float* __restrict__ x, const float* __restrict__ w,
                        const float* __restrict__ b)
{
    int idx = blockIdx.x * blockDim.x + threadIdx.x;
    if (idx < N_DW0) { dw_one(x, g_S0, w, b, 0, 256, true, idx); return; }
    idx -= N_DW0;
    if (idx < N_DW1) { dw_one(g_P1, g_D1, w, b, 1, 128, false, idx); return; }
    idx -= N_DW1;
    if (idx < N_DW2) { dw_one(g_P2, g_D2, w, b, 2, 64, false, idx); return; }
    idx -= N_DW2;
    if (idx < N_DW3) { dw_one(g_P3, g_D3, w, b, 3, 32, false, idx); return; }
}

// ---------------- D -> A fragment conversion (register-local) ----------------
__device__ __forceinline__ void d2a(const float d[][4], int g0, const float* __restrict__ bias,
                                    int lane, uint32_t a[4])
{
    int c0 = 8*g0 + (lane & 3)*2;
    float b00 = __ldg(bias + c0),     b01 = __ldg(bias + c0 + 1);
    float b10 = __ldg(bias + c0 + 8), b11 = __ldg(bias + c0 + 9);
    a[0] = pack2(h16(d[g0][0] + b00),   h16(d[g0][1] + b01));
    a[1] = pack2(h16(d[g0][2] + b00),   h16(d[g0][3] + b01));
    a[2] = pack2(h16(d[g0+1][0] + b10), h16(d[g0+1][1] + b11));
    a[3] = pack2(h16(d[g0+1][2] + b10), h16(d[g0+1][3] + b11));
}

// ---------------- fused kernel: warp-local chain, 256 thr, 8 warps, 2 CTAs/SM ----------------
#define TPC 4
#define NTHR 256
__global__ __launch_bounds__(NTHR, 2)
void fused_mma(const float* __restrict__ x,
               const float* __restrict__ bf1, const float* __restrict__ bf2,
               const float* __restrict__ bf3, float* __restrict__ out)
{
    extern __shared__ __align__(16) unsigned char sm[];
    const uint32_t base = smem_u32(sm);
    const int tid = threadIdx.x;
    const int lane = tid & 31, wid = tid >> 5;   // wid 0..7, owns pixels [wid*16, +16)

    // ---- load all weight images into smem once per CTA (78 KB, L2-hot) ----
    {
        const __half* gs[3] = { g_W1, g_W2, g_W3 };
        const int off[3] = { OFF_W1, OFF_W2, OFF_W3 };
        const int sz[3]  = { 17408, 26112, 34816 };
        #pragma unroll
        for (int a = 0; a < 3; a++) {
            const uint4* s4 = (const uint4*)gs[a];
            for (int i = tid; i < sz[a]/16; i += NTHR)
                sts128(base + off[a] + i*16, s4[i]);
        }
    }

    // per-warp constant addresses
    const uint32_t Abase = base + OFF_A + (uint32_t)(wid*16 + (lane & 15))*APB + ((lane >> 4) << 4);
    // B-operand x4: two 8-row N-tiles per load
    const uint32_t wb_off = (uint32_t)((lane & 7) + ((lane >> 4) << 3))*APB + (((lane >> 3) & 1) << 4);
    const uint32_t W1a = base + OFF_W1 + wb_off;
    const uint32_t W2a = base + OFF_W2 + wb_off;
    const uint32_t W3a = base + OFF_W3 + wb_off;

    float acc[16][4];
    uint32_t areg[6][4];

    for (int t = 0; t < TPC; t++) {
        int tile = blockIdx.x * TPC + t;
        int b = tile >> 9;                // 512 tiles per image
        int rem = (tile & 511) * 128;     // pixel base (half an image row)

        __syncthreads();   // S0: prev-tile epilogue reads done

        // ---- build A (128 px x 128 ch, fp16, 2 ch per sts32) ----
        for (int i = tid; i < 128*64; i += NTHR) {
            int chp = i >> 7, p = i & 127;
            int ch = chp*2;
            int r = rem + p;
            int y = r >> 8, xx = r & 255;
            float v0, v1;
            if (ch < 32) {
                const float* s = &g_S0[((b*32 + ch) << 16) + r];
                v0 = s[0]; v1 = s[1 << 16];
            } else if (ch < 64) {
                const float* s = &g_D1[(b*32 + ch-32)*16384 + (y>>1)*128 + (xx>>1)];
                v0 = s[0]; v1 = s[16384];
            } else if (ch < 96) {
                const float* s = &g_D2[(b*32 + ch-64)*4096 + (y>>2)*64 + (xx>>2)];
                v0 = s[0]; v1 = s[4096];
            } else {
                const float* s = &g_D3[(b*32 + ch-96)*1024 + (y>>3)*32 + (xx>>3)];
                v0 = s[0]; v1 = s[1024];
            }
            sts32(base + OFF_A + (uint32_t)p*APB + ch*2, pack2(h16(v0), h16(v1)));
        }
        __syncthreads();   // S1: A ready (covers W on first tile too)

        // ---- stage 1: res1(64) = W1 @ A[0:64]  (KT=4, NT=8) ----
        #pragma unroll
        for (int n = 0; n < 8; n++)
            #pragma unroll
            for (int i = 0; i < 4; i++) acc[n][i] = 0.0f;
        #pragma unroll
        for (int kt = 0; kt < 4; kt++) {
            uint32_t a[4];
            ldsm_x4(a, Abase + kt*32);
            #pragma unroll
            for (int n2 = 0; n2 < 4; n2++) {
                uint32_t f[4];
                ldsm_x4(f, W1a + (uint32_t)n2*(16*APB) + kt*32);
                mma16816h(acc[2*n2],   a, f[0], f[1]);
                mma16816h(acc[2*n2+1], a, f[2], f[3]);
            }
        }
        #pragma unroll
        for (int j = 0; j < 4; j++) d2a(acc, 2*j, bf1, lane, areg[j]);

        // ---- stage 2: res2(96) = W2 @ [res1; s2]  (KT=6, NT=12) ----
        #pragma unroll
        for (int n = 0; n < 12; n++)
            #pragma unroll
            for (int i = 0; i < 4; i++) acc[n][i] = 0.0f;
        #pragma unroll
        for (int kt = 0; kt < 6; kt++) {
            uint32_t a[4];
            if (kt < 4) { a[0]=areg[kt][0]; a[1]=areg[kt][1]; a[2]=areg[kt][2]; a[3]=areg[kt][3]; }
            else ldsm_x4(a, Abase + kt*32);
            #pragma unroll
            for (int n2 = 0; n2 < 6; n2++) {
                uint32_t f[4];
                ldsm_x4(f, W2a + (uint32_t)n2*(16*APB) + kt*32);
                mma16816h(acc[2*n2],   a, f[0], f[1]);
                mma16816h(acc[2*n2+1], a, f[2], f[3]);
            }
        }
        #pragma unroll
        for (int j = 0; j < 6; j++) d2a(acc, 2*j, bf2, lane, areg[j]);

        // ---- stage 3: res3(128) = W3 @ [res2; s3]  (KT=8, NT=16) ----
        #pragma unroll
        for (int n = 0; n < 16; n++)
            #pragma unroll
            for (int i = 0; i < 4; i++) acc[n][i] = 0.0f;
        #pragma unroll
        for (int kt = 0; kt < 8; kt++) {
            uint32_t a[4];
            if (kt < 6) { a[0]=areg[kt][0]; a[1]=areg[kt][1]; a[2]=areg[kt][2]; a[3]=areg[kt][3]; }
            else ldsm_x4(a, Abase + kt*32);
            #pragma unroll
            for (int n2 = 0; n2 < 8; n2++) {
                uint32_t f[4];
                ldsm_x4(f, W3a + (uint32_t)n2*(16*APB) + kt*32);
                mma16816h(acc[2*n2],   a, f[0], f[1]);
                mma16816h(acc[2*n2+1], a, f[2], f[3]);
            }
        }
        __syncthreads();   // S2: all A-region reads done; epilogue overlays it

        // ---- epilogue: two 64-channel halves via smem transpose ----
        #pragma unroll
        for (int h = 0; h < 2; h++) {
            #pragma unroll
            for (int ntl = 0; ntl < 8; ntl++) {
                int nt = h*8 + ntl;
                int ol = ntl*8 + (lane & 3)*2;       // buffer row (0..63)
                int c  = h*64 + ol;                   // global channel
                float b0 = __ldg(&bf3[c]), b1 = __ldg(&bf3[c+1]);
                int p0 = wid*16 + (lane >> 2);
                #pragma unroll
                for (int hrow = 0; hrow < 2; hrow++) {
                    float v0 = acc[nt][2*hrow+0] + b0;
                    float v1 = acc[nt][2*hrow+1] + b1;
                    float g0 = 0.5f * v0 * (1.0f + erff(v0 * 0.70710678118654752f));
                    float g1 = 0.5f * v1 * (1.0f + erff(v1 * 0.70710678118654752f));
                    int p = p0 + hrow*8;
                    sts32(base + ((uint32_t)ol    *EPITCH + p)*4, __float_as_uint(g0));
                    sts32(base + ((uint32_t)(ol+1)*EPITCH + p)*4, __float_as_uint(g1));
                }
            }
            __syncthreads();
            for (int i = tid; i < 64*32; i += NTHR) {
                int chl = i >> 5, g4 = (i & 31)*4;
                int ch = h*64 + chl;
                size_t gi = ((size_t)(b*128 + ch) << 16) + rem + g4;
                float v0, v1, v2, v3;
                lds128v(v0, v1, v2, v3, base + ((uint32_t)chl*EPITCH + g4)*4);
                float4 xv = *(const float4*)&x[gi];
                float4 o4;
                o4.x = v0 * xv.x; o4.y = v1 * xv.y; o4.z = v2 * xv.z; o4.w = v3 * xv.w;
                *(float4*)&out[gi] = o4;
            }
            __syncthreads();
        }
    }
}

// ---------------- launch ----------------
extern "C" void kernel_launch(void* const* d_in, const int* in_sizes, int n_in,
                              void* d_out, int out_size)
{
    const float* x   = (const float*)d_in[0];
    const float* wdw = (const float*)d_in[1];
    const float* bdw = (const float*)d_in[2];
    const float* wf1 = (const float*)d_in[3];
    const float* bf1 = (const float*)d_in[4];
    const float* wf2 = (const float*)d_in[5];
    const float* bf2 = (const float*)d_in[6];
    const float* wf3 = (const float*)d_in[7];
    const float* bf3 = (const float*)d_in[8];
    float* out = (float*)d_out;
    (void)in_sizes; (void)n_in; (void)out_size;

    cudaFuncSetAttribute(fused_mma, cudaFuncAttributeMaxDynamicSharedMemorySize, SMEM_REQ);

    k_prep<<<(64*64 + 96*96 + 128*128 + 255)/256, 256>>>(wf1, wf2, wf3);      // 0
    k_pool2<<<(BB*CL*128*128)/256, 256>>>(x);                                  // 1
    k_pool4<<<(BB*CL*64*64)/256, 256>>>(x);                                    // 2
    k_pool8<<<(BB*CL*32*32)/256, 256>>>(x);                                    // 3
    k_dwall<<<(N_DW0+N_DW1+N_DW2+N_DW3)/256, 256>>>(x, wdw, bdw);              // 4
    fused_mma<<<1024, NTHR, SMEM_REQ>>>(x, bf1, bf2, bf3, out);                // 5
}

// round 11
// speedup vs baseline: 1.8543x; 1.1415x over previous
#include <cuda_runtime.h>
#include <cuda_fp16.h>
#include <math.h>
#include <stdint.h>

#define BB  8
#define DIM 128
#define CL  32
#define HH  256
#define WW  256

#define APITCH 136            // fp16 elems per row (pitch) of A / weight images
#define APB    (APITCH*2)     // 272 B rows: 17*16 -> ldmatrix-aligned, conflict-free
#define EPITCH 132            // epilogue float pitch (128+4, conflict-free)

// ---------------- device scratch ----------------
// dwconv outputs: packed fp16 channel-pairs, laid out exactly as A-build consumes
__device__ uint32_t g_S0p[BB*16*65536];
__device__ uint32_t g_D1p[BB*16*16384];
__device__ uint32_t g_D2p[BB*16*4096];
__device__ uint32_t g_D3p[BB*16*1024];
// pooled activations (fp32, inputs to dwconv)
__device__ float g_P1[BB*CL*16384];
__device__ float g_T2[BB*CL*16384];   // half-res of level-2 channels
__device__ float g_T3[BB*CL*16384];   // half-res of level-3 channels
__device__ float g_P2[BB*CL*4096];
__device__ float g_P3[BB*CL*1024];

// weight images: shuffle-folded, single fp16, [N][APITCH]
__device__ __align__(16) __half g_W1[64*APITCH];
__device__ __align__(16) __half g_W2[96*APITCH];
__device__ __align__(16) __half g_W3[128*APITCH];

// ---------------- smem layout: A(128x272) + W1+W2+W3 = 110.5 KB -> 2 CTAs/SM ----------------
#define OFF_A   0
#define OFF_W1  34816
#define OFF_W2  52224
#define OFF_W3  78336
#define SMEM_REQ 113152

// ---------------- asm helpers ----------------
__device__ __forceinline__ uint32_t smem_u32(const void* p) {
    uint32_t a;
    asm("{ .reg .u64 t; cvta.to.shared.u64 t, %1; cvt.u32.u64 %0, t; }" : "=r"(a) : "l"(p));
    return a;
}
__device__ __forceinline__ void ldsm_x4(uint32_t r[4], uint32_t addr) {
    asm volatile("ldmatrix.sync.aligned.m8n8.x4.shared.b16 {%0,%1,%2,%3}, [%4];"
        : "=r"(r[0]), "=r"(r[1]), "=r"(r[2]), "=r"(r[3]) : "r"(addr));
}
__device__ __forceinline__ void mma16816h(float d[4], const uint32_t a[4], uint32_t b0, uint32_t b1) {
    asm volatile("mma.sync.aligned.m16n8k16.row.col.f32.f16.f16.f32 "
        "{%0,%1,%2,%3}, {%4,%5,%6,%7}, {%8,%9}, {%0,%1,%2,%3};"
        : "+f"(d[0]), "+f"(d[1]), "+f"(d[2]), "+f"(d[3])
        : "r"(a[0]), "r"(a[1]), "r"(a[2]), "r"(a[3]), "r"(b0), "r"(b1));
}
__device__ __forceinline__ void sts32(uint32_t addr, uint32_t v) {
    asm volatile("st.shared.b32 [%0], %1;" :: "r"(addr), "r"(v) : "memory");
}
__device__ __forceinline__ void sts128(uint32_t addr, uint4 v) {
    asm volatile("st.shared.v4.b32 [%0], {%1,%2,%3,%4};"
        :: "r"(addr), "r"(v.x), "r"(v.y), "r"(v.z), "r"(v.w) : "memory");
}
__device__ __forceinline__ void lds128v(float& a, float& b, float& c, float& d, uint32_t addr) {
    asm volatile("ld.shared.v4.f32 {%0,%1,%2,%3}, [%4];"
        : "=f"(a), "=f"(b), "=f"(c), "=f"(d) : "r"(addr));
}
__device__ __forceinline__ uint16_t h16(float v) {
    return __half_as_ushort(__float2half(v));
}
__device__ __forceinline__ uint32_t pack2(uint16_t a, uint16_t b) {
    return (uint32_t)a | ((uint32_t)b << 16);
}

// ---------------- weight prep: shuffle-fold + fp16 ----------------
__global__ void k_prep(const float* __restrict__ w1, const float* __restrict__ w2,
                       const float* __restrict__ w3)
{
    int t = blockIdx.x * blockDim.x + threadIdx.x;
    float w; __half *ph; int r, k;
    if (t < 64*64) {
        r = t >> 6; k = t & 63;
        w = w1[(r << 6) + ((k & 7) << 3) + (k >> 3)];
        ph = g_W1;
    } else if (t < 64*64 + 96*96) {
        int u = t - 64*64; r = u / 96; k = u % 96;
        w = w2[r*96 + (k % 12)*8 + k/12];
        ph = g_W2;
    } else if (t < 64*64 + 96*96 + 128*128) {
        int u = t - 64*64 - 96*96; r = u >> 7; k = u & 127;
        w = w3[(r << 7) + ((k & 15) << 3) + (k >> 4)];
        ph = g_W3;
    } else return;
    ph[r*APITCH + k] = __float2half(w);
}

// ---------------- pool pass 1: half-res 2x2 max of channels 32..127 of x ----------------
// c<32 -> P1 (level 1), c<64 -> T2 (level 2 intermediate), else T3 (level 3 intermediate)
__global__ void k_poolh(const float* __restrict__ x)
{
    int idx = blockIdx.x * blockDim.x + threadIdx.x;
    if (idx >= BB*96*16384) return;
    int xo = idx & 127;
    int yo = (idx >> 7) & 127;
    int c  = (idx >> 14) % 96;
    int b  = idx / (16384*96);
    const float* p = x + (((size_t)b*DIM + 32 + c)*HH + (size_t)yo*2)*WW + (size_t)xo*2;
    float m = fmaxf(fmaxf(p[0], p[1]), fmaxf(p[WW], p[WW+1]));
    int o = ((b*CL + (c & 31)) << 14) + (yo << 7) + xo;
    if (c < 32)      g_P1[o] = m;
    else if (c < 64) g_T2[o] = m;
    else             g_T3[o] = m;
}

// ---------------- pool pass 2: P2 = pool2(T2) ----------------
__global__ void k_pool2b()
{
    int idx = blockIdx.x * blockDim.x + threadIdx.x;
    if (idx >= BB*CL*4096) return;
    int xo = idx & 63;
    int yo = (idx >> 6) & 63;
    int bc = idx >> 12;
    const float* p = g_T2 + ((size_t)bc << 14) + (size_t)(yo*2)*128 + xo*2;
    g_P2[idx] = fmaxf(fmaxf(p[0], p[1]), fmaxf(p[128], p[129]));
}

// ---------------- pool pass 3: P3 = pool4(T3) ----------------
__global__ void k_pool4c()
{
    int idx = blockIdx.x * blockDim.x + threadIdx.x;
    if (idx >= BB*CL*1024) return;
    int xo = idx & 31;
    int yo = (idx >> 5) & 31;
    int bc = idx >> 10;
    const float* p = g_T3 + ((size_t)bc << 14) + (size_t)(yo*4)*128 + xo*4;
    float m = -3.402823466e38f;
    #pragma unroll
    for (int dy = 0; dy < 4; dy++)
        #pragma unroll
        for (int dx = 0; dx < 4; dx++)
            m = fmaxf(m, p[dy*128 + dx]);
    g_P3[idx] = m;
}

// ---------------- depthwise 3x3, channel PAIRS, fp16-packed output ----------------
__device__ __forceinline__ void dwp(const float* __restrict__ in, uint32_t* __restrict__ out,
                                    const float* __restrict__ w_dw, const float* __restrict__ b_dw,
                                    int lvl, int S, bool from_x, int idx)
{
    int xx = idx % S;
    int yy = (idx / S) % S;
    int cp = (idx / (S*S)) % 16;
    int b  = idx / (S*S*16);
    int c0 = 2*cp;
    const float* ip0 = from_x ? in + ((size_t)b*DIM + lvl*CL + c0) * (size_t)(S*S)
                              : in + ((size_t)b*CL + c0) * (size_t)(S*S);
    const float* ip1 = ip0 + (size_t)(S*S);
    const float* wp0 = w_dw + (lvl*CL + c0) * 9;
    const float* wp1 = wp0 + 9;
    float a0 = b_dw[lvl*CL + c0];
    float a1 = b_dw[lvl*CL + c0 + 1];
    #pragma unroll
    for (int ky = 0; ky < 3; ky++) {
        int iy = yy + ky - 1;
        if ((unsigned)iy >= (unsigned)S) continue;
        #pragma unroll
        for (int kx = 0; kx < 3; kx++) {
            int ix = xx + kx - 1;
            if ((unsigned)ix >= (unsigned)S) continue;
            int o = iy*S + ix;
            a0 = fmaf(wp0[ky*3 + kx], ip0[o], a0);
            a1 = fmaf(wp1[ky*3 + kx], ip1[o], a1);
        }
    }
    out[idx] = pack2(h16(a0), h16(a1));
}
#define N_DW0 (BB*16*65536)
#define N_DW1 (BB*16*16384)
#define N_DW2 (BB*16*4096)
#define N_DW3 (BB*16*1024)
__global__ void k_dwall(const float* __restrict__ x, const float* __restrict__ w,
                        const float* __restrict__ b)
{
    int idx = blockIdx.x * blockDim.x + threadIdx.x;
    if (idx < N_DW0) { dwp(x, g_S0p, w, b, 0, 256, true, idx); return; }
    idx -= N_DW0;
    if (idx < N_DW1) { dwp(g_P1, g_D1p, w, b, 1, 128, false, idx); return; }
    idx -= N_DW1;
    if (idx < N_DW2) { dwp(g_P2, g_D2p, w, b, 2, 64, false, idx); return; }
    idx -= N_DW2;
    if (idx < N_DW3) { dwp(g_P3, g_D3p, w, b, 3, 32, false, idx); return; }
}

// ---------------- D -> A fragment conversion (register-local) ----------------
__device__ __forceinline__ void d2a(const float d[][4], int g0, const float* __restrict__ bias,
                                    int lane, uint32_t a[4])
{
    int c0 = 8*g0 + (lane & 3)*2;
    float b00 = __ldg(bias + c0),     b01 = __ldg(bias + c0 + 1);
    float b10 = __ldg(bias + c0 + 8), b11 = __ldg(bias + c0 + 9);
    a[0] = pack2(h16(d[g0][0] + b00),   h16(d[g0][1] + b01));
    a[1] = pack2(h16(d[g0][2] + b00),   h16(d[g0][3] + b01));
    a[2] = pack2(h16(d[g0+1][0] + b10), h16(d[g0+1][1] + b11));
    a[3] = pack2(h16(d[g0+1][2] + b10), h16(d[g0+1][3] + b11));
}

// ---------------- fused kernel: warp-local chain, 256 thr, 8 warps, 2 CTAs/SM ----------------
#define TPC 4
#define NTHR 256
__global__ __launch_bounds__(NTHR, 2)
void fused_mma(const float* __restrict__ x,
               const float* __restrict__ bf1, const float* __restrict__ bf2,
               const float* __restrict__ bf3, float* __restrict__ out)
{
    extern __shared__ __align__(16) unsigned char sm[];
    const uint32_t base = smem_u32(sm);
    const int tid = threadIdx.x;
    const int lane = tid & 31, wid = tid >> 5;   // wid 0..7, owns pixels [wid*16, +16)

    // ---- load all weight images into smem once per CTA (78 KB, L2-hot) ----
    {
        const __half* gs[3] = { g_W1, g_W2, g_W3 };
        const int off[3] = { OFF_W1, OFF_W2, OFF_W3 };
        const int sz[3]  = { 17408, 26112, 34816 };
        #pragma unroll
        for (int a = 0; a < 3; a++) {
            const uint4* s4 = (const uint4*)gs[a];
            for (int i = tid; i < sz[a]/16; i += NTHR)
                sts128(base + off[a] + i*16, s4[i]);
        }
    }

    // per-warp constant addresses
    const uint32_t Abase = base + OFF_A + (uint32_t)(wid*16 + (lane & 15))*APB + ((lane >> 4) << 4);
    // B-operand x4: two 8-row N-tiles per load
    const uint32_t wb_off = (uint32_t)((lane & 7) + ((lane >> 4) << 3))*APB + (((lane >> 3) & 1) << 4);
    const uint32_t W1a = base + OFF_W1 + wb_off;
    const uint32_t W2a = base + OFF_W2 + wb_off;
    const uint32_t W3a = base + OFF_W3 + wb_off;

    float acc[16][4];
    uint32_t areg[6][4];

    for (int t = 0; t < TPC; t++) {
        int tile = blockIdx.x * TPC + t;
        int b = tile >> 9;                // 512 tiles per image
        int rem = (tile & 511) * 128;     // pixel base (half an image row)

        __syncthreads();   // S0: prev-tile epilogue reads done

        // ---- build A (128 px x 64 fp16 channel-pairs): pure gather + sts32 ----
        for (int i = tid; i < 128*64; i += NTHR) {
            int chp = i >> 7, p = i & 127;
            int r = rem + p;
            int y = r >> 8, xx = r & 255;
            int lvl = chp >> 4, cp = chp & 15;
            uint32_t v;
            if (lvl == 0)      v = g_S0p[((b*16 + cp) << 16) + r];
            else if (lvl == 1) v = g_D1p[(b*16 + cp)*16384 + (y>>1)*128 + (xx>>1)];
            else if (lvl == 2) v = g_D2p[(b*16 + cp)*4096  + (y>>2)*64  + (xx>>2)];
            else               v = g_D3p[(b*16 + cp)*1024  + (y>>3)*32  + (xx>>3)];
            sts32(base + OFF_A + (uint32_t)p*APB + chp*4, v);
        }
        __syncthreads();   // S1: A ready (covers W on first tile too)

        // ---- stage 1: res1(64) = W1 @ A[0:64]  (KT=4, NT=8) ----
        #pragma unroll
        for (int n = 0; n < 8; n++)
            #pragma unroll
            for (int i = 0; i < 4; i++) acc[n][i] = 0.0f;
        #pragma unroll
        for (int kt = 0; kt < 4; kt++) {
            uint32_t a[4];
            ldsm_x4(a, Abase + kt*32);
            #pragma unroll
            for (int n2 = 0; n2 < 4; n2++) {
                uint32_t f[4];
                ldsm_x4(f, W1a + (uint32_t)n2*(16*APB) + kt*32);
                mma16816h(acc[2*n2],   a, f[0], f[1]);
                mma16816h(acc[2*n2+1], a, f[2], f[3]);
            }
        }
        #pragma unroll
        for (int j = 0; j < 4; j++) d2a(acc, 2*j, bf1, lane, areg[j]);

        // ---- stage 2: res2(96) = W2 @ [res1; s2]  (KT=6, NT=12) ----
        #pragma unroll
        for (int n = 0; n < 12; n++)
            #pragma unroll
            for (int i = 0; i < 4; i++) acc[n][i] = 0.0f;
        #pragma unroll
        for (int kt = 0; kt < 6; kt++) {
            uint32_t a[4];
            if (kt < 4) { a[0]=areg[kt][0]; a[1]=areg[kt][1]; a[2]=areg[kt][2]; a[3]=areg[kt][3]; }
            else ldsm_x4(a, Abase + kt*32);
            #pragma unroll
            for (int n2 = 0; n2 < 6; n2++) {
                uint32_t f[4];
                ldsm_x4(f, W2a + (uint32_t)n2*(16*APB) + kt*32);
                mma16816h(acc[2*n2],   a, f[0], f[1]);
                mma16816h(acc[2*n2+1], a, f[2], f[3]);
            }
        }
        #pragma unroll
        for (int j = 0; j < 6; j++) d2a(acc, 2*j, bf2, lane, areg[j]);

        // ---- stage 3: res3(128) = W3 @ [res2; s3]  (KT=8, NT=16) ----
        #pragma unroll
        for (int n = 0; n < 16; n++)
            #pragma unroll
            for (int i = 0; i < 4; i++) acc[n][i] = 0.0f;
        #pragma unroll
        for (int kt = 0; kt < 8; kt++) {
            uint32_t a[4];
            if (kt < 6) { a[0]=areg[kt][0]; a[1]=areg[kt][1]; a[2]=areg[kt][2]; a[3]=areg[kt][3]; }
            else ldsm_x4(a, Abase + kt*32);
            #pragma unroll
            for (int n2 = 0; n2 < 8; n2++) {
                uint32_t f[4];
                ldsm_x4(f, W3a + (uint32_t)n2*(16*APB) + kt*32);
                mma16816h(acc[2*n2],   a, f[0], f[1]);
                mma16816h(acc[2*n2+1], a, f[2], f[3]);
            }
        }
        __syncthreads();   // S2: all A-region reads done; epilogue overlays it

        // ---- epilogue: two 64-channel halves via smem transpose ----
        #pragma unroll
        for (int h = 0; h < 2; h++) {
            #pragma unroll
            for (int ntl = 0; ntl < 8; ntl++) {
                int nt = h*8 + ntl;
                int ol = ntl*8 + (lane & 3)*2;       // buffer row (0..63)
                int c  = h*64 + ol;                   // global channel
                float b0 = __ldg(&bf3[c]), b1 = __ldg(&bf3[c+1]);
                int p0 = wid*16 + (lane >> 2);
                #pragma unroll
                for (int hrow = 0; hrow < 2; hrow++) {
                    float v0 = acc[nt][2*hrow+0] + b0;
                    float v1 = acc[nt][2*hrow+1] + b1;
                    float g0 = 0.5f * v0 * (1.0f + erff(v0 * 0.70710678118654752f));
                    float g1 = 0.5f * v1 * (1.0f + erff(v1 * 0.70710678118654752f));
                    int p = p0 + hrow*8;
                    sts32(base + ((uint32_t)ol    *EPITCH + p)*4, __float_as_uint(g0));
                    sts32(base + ((uint32_t)(ol+1)*EPITCH + p)*4, __float_as_uint(g1));
                }
            }
            __syncthreads();
            for (int i = tid; i < 64*32; i += NTHR) {
                int chl = i >> 5, g4 = (i & 31)*4;
                int ch = h*64 + chl;
                size_t gi = ((size_t)(b*128 + ch) << 16) + rem + g4;
                float v0, v1, v2, v3;
                lds128v(v0, v1, v2, v3, base + ((uint32_t)chl*EPITCH + g4)*4);
                float4 xv = *(const float4*)&x[gi];
                float4 o4;
                o4.x = v0 * xv.x; o4.y = v1 * xv.y; o4.z = v2 * xv.z; o4.w = v3 * xv.w;
                *(float4*)&out[gi] = o4;
            }
            __syncthreads();
        }
    }
}

// ---------------- launch ----------------
extern "C" void kernel_launch(void* const* d_in, const int* in_sizes, int n_in,
                              void* d_out, int out_size)
{
    const float* x   = (const float*)d_in[0];
    const float* wdw = (const float*)d_in[1];
    const float* bdw = (const float*)d_in[2];
    const float* wf1 = (const float*)d_in[3];
    const float* bf1 = (const float*)d_in[4];
    const float* wf2 = (const float*)d_in[5];
    const float* bf2 = (const float*)d_in[6];
    const float* wf3 = (const float*)d_in[7];
    const float* bf3 = (const float*)d_in[8];
    float* out = (float*)d_out;
    (void)in_sizes; (void)n_in; (void)out_size;

    cudaFuncSetAttribute(fused_mma, cudaFuncAttributeMaxDynamicSharedMemorySize, SMEM_REQ);

    k_prep<<<(64*64 + 96*96 + 128*128 + 255)/256, 256>>>(wf1, wf2, wf3);      // 0
    k_poolh<<<(BB*96*16384 + 255)/256, 256>>>(x);                              // 1
    k_pool2b<<<(BB*CL*4096 + 255)/256, 256>>>();                               // 2
    k_pool4c<<<(BB*CL*1024 + 255)/256, 256>>>();                               // 3
    k_dwall<<<(N_DW0+N_DW1+N_DW2+N_DW3 + 255)/256, 256>>>(x, wdw, bdw);        // 4
    fused_mma<<<1024, NTHR, SMEM_REQ>>>(x, bf1, bf2, bf3, out);                // 5
}

// round 12
// speedup vs baseline: 1.9510x; 1.0522x over previous
#include <cuda_runtime.h>
#include <cuda_fp16.h>
#include <math.h>
#include <stdint.h>

#define BB  8
#define DIM 128
#define CL  32
#define HH  256
#define WW  256

#define APITCH 136            // fp16 elems per row (pitch) of A / weight images
#define APB    (APITCH*2)     // 272 B rows: 17*16 -> ldmatrix-aligned, conflict-free

// ---------------- device scratch ----------------
// dwconv outputs: packed fp16 channel-pairs, laid out exactly as A-build consumes
__device__ uint32_t g_S0p[BB*16*65536];
__device__ uint32_t g_D1p[BB*16*16384];
__device__ uint32_t g_D2p[BB*16*4096];
__device__ uint32_t g_D3p[BB*16*1024];
// pooled activations (fp32, inputs to dwconv)
__device__ float g_P1[BB*CL*16384];
__device__ float g_T2[BB*CL*16384];
__device__ float g_T3[BB*CL*16384];
__device__ float g_P2[BB*CL*4096];
__device__ float g_P3[BB*CL*1024];

// weight images: shuffle-folded, single fp16, [N][APITCH]
__device__ __align__(16) __half g_W1[64*APITCH];
__device__ __align__(16) __half g_W2[96*APITCH];
__device__ __align__(16) __half g_W3[128*APITCH];

// ---------------- smem layout: A(128x272) + W1+W2+W3 = 110.5 KB -> 2 CTAs/SM ----------------
#define OFF_A   0
#define OFF_W1  34816
#define OFF_W2  52224
#define OFF_W3  78336
#define SMEM_REQ 113152

// ---------------- asm helpers ----------------
__device__ __forceinline__ uint32_t smem_u32(const void* p) {
    uint32_t a;
    asm("{ .reg .u64 t; cvta.to.shared.u64 t, %1; cvt.u32.u64 %0, t; }" : "=r"(a) : "l"(p));
    return a;
}
__device__ __forceinline__ void ldsm_x4(uint32_t r[4], uint32_t addr) {
    asm volatile("ldmatrix.sync.aligned.m8n8.x4.shared.b16 {%0,%1,%2,%3}, [%4];"
        : "=r"(r[0]), "=r"(r[1]), "=r"(r[2]), "=r"(r[3]) : "r"(addr));
}
__device__ __forceinline__ void mma16816h(float d[4], const uint32_t a[4], uint32_t b0, uint32_t b1) {
    asm volatile("mma.sync.aligned.m16n8k16.row.col.f32.f16.f16.f32 "
        "{%0,%1,%2,%3}, {%4,%5,%6,%7}, {%8,%9}, {%0,%1,%2,%3};"
        : "+f"(d[0]), "+f"(d[1]), "+f"(d[2]), "+f"(d[3])
        : "r"(a[0]), "r"(a[1]), "r"(a[2]), "r"(a[3]), "r"(b0), "r"(b1));
}
__device__ __forceinline__ void sts32(uint32_t addr, uint32_t v) {
    asm volatile("st.shared.b32 [%0], %1;" :: "r"(addr), "r"(v) : "memory");
}
__device__ __forceinline__ void sts128(uint32_t addr, uint4 v) {
    asm volatile("st.shared.v4.b32 [%0], {%1,%2,%3,%4};"
        :: "r"(addr), "r"(v.x), "r"(v.y), "r"(v.z), "r"(v.w) : "memory");
}
__device__ __forceinline__ uint16_t h16(float v) {
    return __half_as_ushort(__float2half(v));
}
__device__ __forceinline__ uint32_t pack2(uint16_t a, uint16_t b) {
    return (uint32_t)a | ((uint32_t)b << 16);
}

// ---------------- weight prep: shuffle-fold + fp16 ----------------
__global__ void k_prep(const float* __restrict__ w1, const float* __restrict__ w2,
                       const float* __restrict__ w3)
{
    int t = blockIdx.x * blockDim.x + threadIdx.x;
    float w; __half *ph; int r, k;
    if (t < 64*64) {
        r = t >> 6; k = t & 63;
        w = w1[(r << 6) + ((k & 7) << 3) + (k >> 3)];
        ph = g_W1;
    } else if (t < 64*64 + 96*96) {
        int u = t - 64*64; r = u / 96; k = u % 96;
        w = w2[r*96 + (k % 12)*8 + k/12];
        ph = g_W2;
    } else if (t < 64*64 + 96*96 + 128*128) {
        int u = t - 64*64 - 96*96; r = u >> 7; k = u & 127;
        w = w3[(r << 7) + ((k & 15) << 3) + (k >> 4)];
        ph = g_W3;
    } else return;
    ph[r*APITCH + k] = __float2half(w);
}

// ---------------- pool pass 1: half-res 2x2 max of channels 32..127 of x ----------------
__global__ void k_poolh(const float* __restrict__ x)
{
    int idx = blockIdx.x * blockDim.x + threadIdx.x;
    if (idx >= BB*96*16384) return;
    int xo = idx & 127;
    int yo = (idx >> 7) & 127;
    int c  = (idx >> 14) % 96;
    int b  = idx / (16384*96);
    const float* p = x + (((size_t)b*DIM + 32 + c)*HH + (size_t)yo*2)*WW + (size_t)xo*2;
    float m = fmaxf(fmaxf(p[0], p[1]), fmaxf(p[WW], p[WW+1]));
    int o = ((b*CL + (c & 31)) << 14) + (yo << 7) + xo;
    if (c < 32)      g_P1[o] = m;
    else if (c < 64) g_T2[o] = m;
    else             g_T3[o] = m;
}

// ---------------- pool pass 2: P2 = pool2(T2) ----------------
__global__ void k_pool2b()
{
    int idx = blockIdx.x * blockDim.x + threadIdx.x;
    if (idx >= BB*CL*4096) return;
    int xo = idx & 63;
    int yo = (idx >> 6) & 63;
    int bc = idx >> 12;
    const float* p = g_T2 + ((size_t)bc << 14) + (size_t)(yo*2)*128 + xo*2;
    g_P2[idx] = fmaxf(fmaxf(p[0], p[1]), fmaxf(p[128], p[129]));
}

// ---------------- pool pass 3: P3 = pool4(T3) ----------------
__global__ void k_pool4c()
{
    int idx = blockIdx.x * blockDim.x + threadIdx.x;
    if (idx >= BB*CL*1024) return;
    int xo = idx & 31;
    int yo = (idx >> 5) & 31;
    int bc = idx >> 10;
    const float* p = g_T3 + ((size_t)bc << 14) + (size_t)(yo*4)*128 + xo*4;
    float m = -3.402823466e38f;
    #pragma unroll
    for (int dy = 0; dy < 4; dy++)
        #pragma unroll
        for (int dx = 0; dx < 4; dx++)
            m = fmaxf(m, p[dy*128 + dx]);
    g_P3[idx] = m;
}

// ---------------- depthwise 3x3, channel PAIRS, fp16-packed output ----------------
__device__ __forceinline__ void dwp(const float* __restrict__ in, uint32_t* __restrict__ out,
                                    const float* __restrict__ w_dw, const float* __restrict__ b_dw,
                                    int lvl, int S, bool from_x, int idx)
{
    int xx = idx % S;
    int yy = (idx / S) % S;
    int cp = (idx / (S*S)) % 16;
    int b  = idx / (S*S*16);
    int c0 = 2*cp;
    const float* ip0 = from_x ? in + ((size_t)b*DIM + lvl*CL + c0) * (size_t)(S*S)
                              : in + ((size_t)b*CL + c0) * (size_t)(S*S);
    const float* ip1 = ip0 + (size_t)(S*S);
    const float* wp0 = w_dw + (lvl*CL + c0) * 9;
    const float* wp1 = wp0 + 9;
    float a0 = b_dw[lvl*CL + c0];
    float a1 = b_dw[lvl*CL + c0 + 1];
    #pragma unroll
    for (int ky = 0; ky < 3; ky++) {
        int iy = yy + ky - 1;
        if ((unsigned)iy >= (unsigned)S) continue;
        #pragma unroll
        for (int kx = 0; kx < 3; kx++) {
            int ix = xx + kx - 1;
            if ((unsigned)ix >= (unsigned)S) continue;
            int o = iy*S + ix;
            a0 = fmaf(wp0[ky*3 + kx], ip0[o], a0);
            a1 = fmaf(wp1[ky*3 + kx], ip1[o], a1);
        }
    }
    out[idx] = pack2(h16(a0), h16(a1));
}
#define N_DW0 (BB*16*65536)
#define N_DW1 (BB*16*16384)
#define N_DW2 (BB*16*4096)
#define N_DW3 (BB*16*1024)
__global__ void k_dwall(const float* __restrict__ x, const float* __restrict__ w,
                        const float* __restrict__ b)
{
    int idx = blockIdx.x * blockDim.x + threadIdx.x;
    if (idx < N_DW0) { dwp(x, g_S0p, w, b, 0, 256, true, idx); return; }
    idx -= N_DW0;
    if (idx < N_DW1) { dwp(g_P1, g_D1p, w, b, 1, 128, false, idx); return; }
    idx -= N_DW1;
    if (idx < N_DW2) { dwp(g_P2, g_D2p, w, b, 2, 64, false, idx); return; }
    idx -= N_DW2;
    if (idx < N_DW3) { dwp(g_P3, g_D3p, w, b, 3, 32, false, idx); return; }
}

// ---------------- D -> A fragment conversion (register-local) ----------------
__device__ __forceinline__ void d2a(const float d[][4], int g0, const float* __restrict__ bias,
                                    int lane, uint32_t a[4])
{
    int c0 = 8*g0 + (lane & 3)*2;
    float b00 = __ldg(bias + c0),     b01 = __ldg(bias + c0 + 1);
    float b10 = __ldg(bias + c0 + 8), b11 = __ldg(bias + c0 + 9);
    a[0] = pack2(h16(d[g0][0] + b00),   h16(d[g0][1] + b01));
    a[1] = pack2(h16(d[g0][2] + b00),   h16(d[g0][3] + b01));
    a[2] = pack2(h16(d[g0+1][0] + b10), h16(d[g0+1][1] + b11));
    a[3] = pack2(h16(d[g0+1][2] + b10), h16(d[g0+1][3] + b11));
}

// ---------------- fused kernel: warp-local chain, 256 thr, 8 warps, 2 CTAs/SM ----------------
#define TPC 4
#define NTHR 256
__global__ __launch_bounds__(NTHR, 2)
void fused_mma(const float* __restrict__ x,
               const float* __restrict__ bf1, const float* __restrict__ bf2,
               const float* __restrict__ bf3, float* __restrict__ out)
{
    extern __shared__ __align__(16) unsigned char sm[];
    const uint32_t base = smem_u32(sm);
    const int tid = threadIdx.x;
    const int lane = tid & 31, wid = tid >> 5;   // wid 0..7, owns pixels [wid*16, +16)

    // ---- load all weight images into smem once per CTA (78 KB, L2-hot) ----
    {
        const __half* gs[3] = { g_W1, g_W2, g_W3 };
        const int off[3] = { OFF_W1, OFF_W2, OFF_W3 };
        const int sz[3]  = { 17408, 26112, 34816 };
        #pragma unroll
        for (int a = 0; a < 3; a++) {
            const uint4* s4 = (const uint4*)gs[a];
            for (int i = tid; i < sz[a]/16; i += NTHR)
                sts128(base + off[a] + i*16, s4[i]);
        }
    }

    // per-warp constant addresses
    const uint32_t Abase = base + OFF_A + (uint32_t)(wid*16 + (lane & 15))*APB + ((lane >> 4) << 4);
    const uint32_t wb_off = (uint32_t)((lane & 7) + ((lane >> 4) << 3))*APB + (((lane >> 3) & 1) << 4);
    const uint32_t W1a = base + OFF_W1 + wb_off;
    const uint32_t W2a = base + OFF_W2 + wb_off;
    const uint32_t W3a = base + OFF_W3 + wb_off;

    float acc[16][4];
    uint32_t areg[6][4];

    for (int t = 0; t < TPC; t++) {
        int tile = blockIdx.x * TPC + t;
        int b = tile >> 9;                // 512 tiles per image
        int rem = (tile & 511) * 128;     // pixel base (half an image row)

        // ---- build A (128 px x 64 fp16 channel-pairs): pure gather + sts32 ----
        for (int i = tid; i < 128*64; i += NTHR) {
            int chp = i >> 7, p = i & 127;
            int r = rem + p;
            int y = r >> 8, xx = r & 255;
            int lvl = chp >> 4, cp = chp & 15;
            uint32_t v;
            if (lvl == 0)      v = g_S0p[((b*16 + cp) << 16) + r];
            else if (lvl == 1) v = g_D1p[(b*16 + cp)*16384 + (y>>1)*128 + (xx>>1)];
            else if (lvl == 2) v = g_D2p[(b*16 + cp)*4096  + (y>>2)*64  + (xx>>2)];
            else               v = g_D3p[(b*16 + cp)*1024  + (y>>3)*32  + (xx>>3)];
            sts32(base + OFF_A + (uint32_t)p*APB + chp*4, v);
        }
        __syncthreads();   // S1: A ready (covers W load on first tile too)

        // ---- stage 1: res1(64) = W1 @ A[0:64]  (KT=4, NT=8) ----
        #pragma unroll
        for (int n = 0; n < 8; n++)
            #pragma unroll
            for (int i = 0; i < 4; i++) acc[n][i] = 0.0f;
        #pragma unroll
        for (int kt = 0; kt < 4; kt++) {
            uint32_t a[4];
            ldsm_x4(a, Abase + kt*32);
            #pragma unroll
            for (int n2 = 0; n2 < 4; n2++) {
                uint32_t f[4];
                ldsm_x4(f, W1a + (uint32_t)n2*(16*APB) + kt*32);
                mma16816h(acc[2*n2],   a, f[0], f[1]);
                mma16816h(acc[2*n2+1], a, f[2], f[3]);
            }
        }
        #pragma unroll
        for (int j = 0; j < 4; j++) d2a(acc, 2*j, bf1, lane, areg[j]);

        // ---- stage 2: res2(96) = W2 @ [res1; s2]  (KT=6, NT=12) ----
        #pragma unroll
        for (int n = 0; n < 12; n++)
            #pragma unroll
            for (int i = 0; i < 4; i++) acc[n][i] = 0.0f;
        #pragma unroll
        for (int kt = 0; kt < 6; kt++) {
            uint32_t a[4];
            if (kt < 4) { a[0]=areg[kt][0]; a[1]=areg[kt][1]; a[2]=areg[kt][2]; a[3]=areg[kt][3]; }
            else ldsm_x4(a, Abase + kt*32);
            #pragma unroll
            for (int n2 = 0; n2 < 6; n2++) {
                uint32_t f[4];
                ldsm_x4(f, W2a + (uint32_t)n2*(16*APB) + kt*32);
                mma16816h(acc[2*n2],   a, f[0], f[1]);
                mma16816h(acc[2*n2+1], a, f[2], f[3]);
            }
        }
        #pragma unroll
        for (int j = 0; j < 6; j++) d2a(acc, 2*j, bf2, lane, areg[j]);

        // ---- stage 3: res3(128) = W3 @ [res2; s3]  (KT=8, NT=16) ----
        #pragma unroll
        for (int n = 0; n < 16; n++)
            #pragma unroll
            for (int i = 0; i < 4; i++) acc[n][i] = 0.0f;
        #pragma unroll
        for (int kt = 0; kt < 8; kt++) {
            uint32_t a[4];
            if (kt < 6) { a[0]=areg[kt][0]; a[1]=areg[kt][1]; a[2]=areg[kt][2]; a[3]=areg[kt][3]; }
            else ldsm_x4(a, Abase + kt*32);
            #pragma unroll
            for (int n2 = 0; n2 < 8; n2++) {
                uint32_t f[4];
                ldsm_x4(f, W3a + (uint32_t)n2*(16*APB) + kt*32);
                mma16816h(acc[2*n2],   a, f[0], f[1]);
                mma16816h(acc[2*n2+1], a, f[2], f[3]);
            }
        }
        __syncthreads();   // S2: all A-region reads done; next tile may overwrite

        // ---- epilogue: gelu(res3+b3)*x, DIRECT sector-aligned global stores ----
        // For fixed (nt,hrow,ch): lanes with equal lane&3 hold 8 consecutive pixels
        // -> each 4B-store instruction moves 4 full 32B sectors (100% efficiency).
        {
            const int p0 = wid*16 + (lane >> 2);
            #pragma unroll
            for (int nt = 0; nt < 16; nt++) {
                int c0 = nt*8 + (lane & 3)*2;
                float b0 = __ldg(&bf3[c0]), b1 = __ldg(&bf3[c0+1]);
                size_t g0i = ((size_t)(b*128 + c0) << 16) + rem;
                size_t g1i = g0i + 65536;
                #pragma unroll
                for (int hrow = 0; hrow < 2; hrow++) {
                    int p = p0 + hrow*8;
                    float v0 = acc[nt][2*hrow+0] + b0;
                    float v1 = acc[nt][2*hrow+1] + b1;
                    float e0 = 0.5f * v0 * (1.0f + erff(v0 * 0.70710678118654752f));
                    float e1 = 0.5f * v1 * (1.0f + erff(v1 * 0.70710678118654752f));
                    out[g0i + p] = e0 * __ldg(&x[g0i + p]);
                    out[g1i + p] = e1 * __ldg(&x[g1i + p]);
                }
            }
        }
    }
}

// ---------------- launch ----------------
extern "C" void kernel_launch(void* const* d_in, const int* in_sizes, int n_in,
                              void* d_out, int out_size)
{
    const float* x   = (const float*)d_in[0];
    const float* wdw = (const float*)d_in[1];
    const float* bdw = (const float*)d_in[2];
    const float* wf1 = (const float*)d_in[3];
    const float* bf1 = (const float*)d_in[4];
    const float* wf2 = (const float*)d_in[5];
    const float* bf2 = (const float*)d_in[6];
    const float* wf3 = (const float*)d_in[7];
    const float* bf3 = (const float*)d_in[8];
    float* out = (float*)d_out;
    (void)in_sizes; (void)n_in; (void)out_size;

    cudaFuncSetAttribute(fused_mma, cudaFuncAttributeMaxDynamicSharedMemorySize, SMEM_REQ);

    k_prep<<<(64*64 + 96*96 + 128*128 + 255)/256, 256>>>(wf1, wf2, wf3);      // 0
    k_poolh<<<(BB*96*16384 + 255)/256, 256>>>(x);                              // 1
    k_pool2b<<<(BB*CL*4096 + 255)/256, 256>>>();                               // 2
    k_pool4c<<<(BB*CL*1024 + 255)/256, 256>>>();                               // 3
    k_dwall<<<(N_DW0+N_DW1+N_DW2+N_DW3 + 255)/256, 256>>>(x, wdw, bdw);        // 4
    fused_mma<<<1024, NTHR, SMEM_REQ>>>(x, bf1, bf2, bf3, out);                // 5
}